// round 4
// baseline (speedup 1.0000x reference)
#include <cuda_runtime.h>
#include <cuda_bf16.h>
#include <cstdint>
#include <cstddef>

// ---------------------------------------------------------------------------
// Mamba model, fp32 baseline.
// Shapes: B=4, S=2048, D_MODEL=256, D_INNER=512, D_STATE=16, DT_RANK=16,
//         D_CONV=4, N_LAYERS=4.
// Layouts: h/res/hn/xz are (b,s,feature) row-major; xc/zt/dt/y are TRANSPOSED
//          (b, d, s) so the sequential scan streams contiguously over time;
//          dblt is (b, j, s) with j: 0..15 dt_pre, 16..31 B, 32..47 C.
// ---------------------------------------------------------------------------

#define NB     4
#define NS     2048
#define DM     256
#define DI     512
#define DSTATE 16
#define NTOK   (NB * NS)          // 8192

// scratch (static device allocations -- allowed)
__device__ float g_h   [NTOK * DM];          // 8 MB
__device__ float g_res [NTOK * DM];          // 8 MB
__device__ float g_hn  [NTOK * DM];          // 8 MB
__device__ float g_xz  [NTOK * 2 * DI];      // 32 MB  (b,s,1024): xh | z
__device__ float g_xc  [NB * DI * NS];       // 16 MB  (b,d,s) conv+silu output
__device__ float g_zt  [NB * DI * NS];       // 16 MB  (b,d,s) silu(z)
__device__ float g_dblt[NB * 48 * NS];       // 1.5 MB (b,j,s)
__device__ float g_dt  [NB * DI * NS];       // 16 MB  (b,d,s) softplus dt
__device__ float g_y   [NB * DI * NS];       // 16 MB  (b,d,s) scan output (gated)

// ---------------------------------------------------------------------------
// embed: h[row,m] = sum_{k<15} x[row,k] * in_W[m,k]
// ---------------------------------------------------------------------------
__global__ __launch_bounds__(256)
void embed_kernel(const float* __restrict__ x, const float* __restrict__ W,
                  float* __restrict__ h) {
    __shared__ float xs[15];
    int row = blockIdx.x;
    if (threadIdx.x < 15) xs[threadIdx.x] = x[row * 15 + threadIdx.x];
    __syncthreads();
    int m = threadIdx.x;
    const float* wr = W + m * 15;
    float acc = 0.f;
#pragma unroll
    for (int k = 0; k < 15; k++) acc = fmaf(xs[k], wr[k], acc);
    h[(size_t)row * DM + m] = acc;
}

// ---------------------------------------------------------------------------
// fused residual + layernorm; one warp per row of 256
// ---------------------------------------------------------------------------
__global__ __launch_bounds__(256)
void ln_kernel(const float* __restrict__ hin, float* __restrict__ res,
               float* __restrict__ hn, const float* __restrict__ w,
               const float* __restrict__ bb, int first) {
    int wid = threadIdx.x >> 5, lane = threadIdx.x & 31;
    int row = blockIdx.x * 8 + wid;
    const float* hp = hin + (size_t)row * DM;
    float* rp = res + (size_t)row * DM;
    float* op = hn + (size_t)row * DM;
    int c0 = lane * 4, c1 = 128 + lane * 4;
    float4 v0 = *(const float4*)(hp + c0);
    float4 v1 = *(const float4*)(hp + c1);
    if (!first) {
        float4 r0 = *(const float4*)(rp + c0);
        float4 r1 = *(const float4*)(rp + c1);
        v0.x += r0.x; v0.y += r0.y; v0.z += r0.z; v0.w += r0.w;
        v1.x += r1.x; v1.y += r1.y; v1.z += r1.z; v1.w += r1.w;
    }
    *(float4*)(rp + c0) = v0;
    *(float4*)(rp + c1) = v1;
    float s = v0.x + v0.y + v0.z + v0.w + v1.x + v1.y + v1.z + v1.w;
    float q = v0.x*v0.x + v0.y*v0.y + v0.z*v0.z + v0.w*v0.w +
              v1.x*v1.x + v1.y*v1.y + v1.z*v1.z + v1.w*v1.w;
#pragma unroll
    for (int o = 16; o > 0; o >>= 1) {
        s += __shfl_xor_sync(0xffffffffu, s, o);
        q += __shfl_xor_sync(0xffffffffu, q, o);
    }
    float m  = s * (1.f / 256.f);
    float var = q * (1.f / 256.f) - m * m;
    float rstd = rsqrtf(var + 1e-5f);
    float4 w0 = *(const float4*)(w + c0), w1 = *(const float4*)(w + c1);
    float4 b0 = *(const float4*)(bb + c0), b1 = *(const float4*)(bb + c1);
    float4 o0, o1;
    o0.x = (v0.x - m) * rstd * w0.x + b0.x;
    o0.y = (v0.y - m) * rstd * w0.y + b0.y;
    o0.z = (v0.z - m) * rstd * w0.z + b0.z;
    o0.w = (v0.w - m) * rstd * w0.w + b0.w;
    o1.x = (v1.x - m) * rstd * w1.x + b1.x;
    o1.y = (v1.y - m) * rstd * w1.y + b1.y;
    o1.z = (v1.z - m) * rstd * w1.z + b1.z;
    o1.w = (v1.w - m) * rstd * w1.w + b1.w;
    *(float4*)(op + c0) = o0;
    *(float4*)(op + c1) = o1;
}

// ---------------------------------------------------------------------------
// GEMM NT: C[M,N] = A(M,K) * B(N,K)^T, both row-major. Tile 128x64x16.
// ---------------------------------------------------------------------------
__global__ __launch_bounds__(256)
void gemm_nt(const float* __restrict__ A, const float* __restrict__ B,
             float* __restrict__ C, int M, int N, int K) {
    __shared__ float As[16][128];
    __shared__ float Bs[16][64];
    int tid = threadIdx.x;
    int m0 = blockIdx.y * 128, n0 = blockIdx.x * 64;
    int la_m = tid >> 1;            // 0..127
    int la_k = (tid & 1) * 8;       // 0,8
    int lb_n = tid >> 2;            // 0..63
    int lb_k = (tid & 3) * 4;       // 0..12
    int ty = tid >> 4, tx = tid & 15;
    float acc[8][4];
#pragma unroll
    for (int i = 0; i < 8; i++)
#pragma unroll
        for (int j = 0; j < 4; j++) acc[i][j] = 0.f;
    const float* Ap = A + (size_t)(m0 + la_m) * K + la_k;
    const float* Bp = B + (size_t)(n0 + lb_n) * K + lb_k;
    for (int k0 = 0; k0 < K; k0 += 16) {
        float4 a0 = *(const float4*)(Ap + k0);
        float4 a1 = *(const float4*)(Ap + k0 + 4);
        float4 b0 = *(const float4*)(Bp + k0);
        __syncthreads();
        As[la_k + 0][la_m] = a0.x; As[la_k + 1][la_m] = a0.y;
        As[la_k + 2][la_m] = a0.z; As[la_k + 3][la_m] = a0.w;
        As[la_k + 4][la_m] = a1.x; As[la_k + 5][la_m] = a1.y;
        As[la_k + 6][la_m] = a1.z; As[la_k + 7][la_m] = a1.w;
        Bs[lb_k + 0][lb_n] = b0.x; Bs[lb_k + 1][lb_n] = b0.y;
        Bs[lb_k + 2][lb_n] = b0.z; Bs[lb_k + 3][lb_n] = b0.w;
        __syncthreads();
#pragma unroll
        for (int kk = 0; kk < 16; kk++) {
            float4 av0 = *(const float4*)&As[kk][ty * 8];
            float4 av1 = *(const float4*)&As[kk][ty * 8 + 4];
            float4 bv  = *(const float4*)&Bs[kk][tx * 4];
            float am[8] = {av0.x, av0.y, av0.z, av0.w, av1.x, av1.y, av1.z, av1.w};
            float bn[4] = {bv.x, bv.y, bv.z, bv.w};
#pragma unroll
            for (int i = 0; i < 8; i++)
#pragma unroll
                for (int j = 0; j < 4; j++)
                    acc[i][j] = fmaf(am[i], bn[j], acc[i][j]);
        }
    }
#pragma unroll
    for (int i = 0; i < 8; i++) {
        float4 o = make_float4(acc[i][0], acc[i][1], acc[i][2], acc[i][3]);
        *(float4*)(C + (size_t)(m0 + ty * 8 + i) * N + n0 + tx * 4) = o;
    }
}

// ---------------------------------------------------------------------------
// GEMM TN: C[M,N] = A_mem(K,M)^T * B(N,K)^T; batched over blockIdx.z.
// ---------------------------------------------------------------------------
__global__ __launch_bounds__(256)
void gemm_tn(const float* __restrict__ A, const float* __restrict__ B,
             float* __restrict__ C, int M, int N, int K,
             size_t sAb, size_t sCb) {
    __shared__ float As[16][128];
    __shared__ float Bs[16][64];
    int bz = blockIdx.z;
    const float* Ab = A + (size_t)bz * sAb;
    float* Cb = C + (size_t)bz * sCb;
    int tid = threadIdx.x;
    int m0 = blockIdx.y * 128, n0 = blockIdx.x * 64;
    int la_k = tid >> 4;            // 0..15
    int la_m = (tid & 15) * 8;      // 0..120
    int lb_n = tid >> 2;
    int lb_k = (tid & 3) * 4;
    int ty = tid >> 4, tx = tid & 15;
    float acc[8][4];
#pragma unroll
    for (int i = 0; i < 8; i++)
#pragma unroll
        for (int j = 0; j < 4; j++) acc[i][j] = 0.f;
    const float* Ap = Ab + (size_t)la_k * M + m0 + la_m;
    const float* Bp = B + (size_t)(n0 + lb_n) * K + lb_k;
    for (int k0 = 0; k0 < K; k0 += 16) {
        float4 a0 = *(const float4*)(Ap + (size_t)k0 * M);
        float4 a1 = *(const float4*)(Ap + (size_t)k0 * M + 4);
        float4 b0 = *(const float4*)(Bp + k0);
        __syncthreads();
        *(float4*)&As[la_k][la_m]     = a0;
        *(float4*)&As[la_k][la_m + 4] = a1;
        Bs[lb_k + 0][lb_n] = b0.x; Bs[lb_k + 1][lb_n] = b0.y;
        Bs[lb_k + 2][lb_n] = b0.z; Bs[lb_k + 3][lb_n] = b0.w;
        __syncthreads();
#pragma unroll
        for (int kk = 0; kk < 16; kk++) {
            float4 av0 = *(const float4*)&As[kk][ty * 8];
            float4 av1 = *(const float4*)&As[kk][ty * 8 + 4];
            float4 bv  = *(const float4*)&Bs[kk][tx * 4];
            float am[8] = {av0.x, av0.y, av0.z, av0.w, av1.x, av1.y, av1.z, av1.w};
            float bn[4] = {bv.x, bv.y, bv.z, bv.w};
#pragma unroll
            for (int i = 0; i < 8; i++)
#pragma unroll
                for (int j = 0; j < 4; j++)
                    acc[i][j] = fmaf(am[i], bn[j], acc[i][j]);
        }
    }
#pragma unroll
    for (int i = 0; i < 8; i++) {
        float4 o = make_float4(acc[i][0], acc[i][1], acc[i][2], acc[i][3]);
        *(float4*)(Cb + (size_t)(m0 + ty * 8 + i) * N + n0 + tx * 4) = o;
    }
}

// ---------------------------------------------------------------------------
// xproj: per batch, C_t(j,s) = xpW(48,512) applied to xc (K=512, M=2048).
// Same as gemm_tn with N=48 guard and transposed epilogue into dblt (b,j,s).
// ---------------------------------------------------------------------------
__global__ __launch_bounds__(256)
void xproj_kernel(const float* __restrict__ A, const float* __restrict__ B,
                  float* __restrict__ Ct) {
    const int M = NS, K = DI;
    __shared__ float As[16][128];
    __shared__ float Bs[16][64];
    int bz = blockIdx.z;
    const float* Ab = A + (size_t)bz * DI * NS;
    float* Cb = Ct + (size_t)bz * 48 * NS;
    int tid = threadIdx.x;
    int m0 = blockIdx.y * 128;
    int la_k = tid >> 4;
    int la_m = (tid & 15) * 8;
    int lb_n = tid >> 2;       // 0..63 (only <48 valid)
    int lb_k = (tid & 3) * 4;
    int ty = tid >> 4, tx = tid & 15;
    float acc[8][4];
#pragma unroll
    for (int i = 0; i < 8; i++)
#pragma unroll
        for (int j = 0; j < 4; j++) acc[i][j] = 0.f;
    const float* Ap = Ab + (size_t)la_k * M + m0 + la_m;
    const float* Bp = B + (size_t)lb_n * K + lb_k;
    bool bvalid = (lb_n < 48);
    for (int k0 = 0; k0 < K; k0 += 16) {
        float4 a0 = *(const float4*)(Ap + (size_t)k0 * M);
        float4 a1 = *(const float4*)(Ap + (size_t)k0 * M + 4);
        float4 b0 = bvalid ? *(const float4*)(Bp + k0)
                           : make_float4(0.f, 0.f, 0.f, 0.f);
        __syncthreads();
        *(float4*)&As[la_k][la_m]     = a0;
        *(float4*)&As[la_k][la_m + 4] = a1;
        Bs[lb_k + 0][lb_n] = b0.x; Bs[lb_k + 1][lb_n] = b0.y;
        Bs[lb_k + 2][lb_n] = b0.z; Bs[lb_k + 3][lb_n] = b0.w;
        __syncthreads();
#pragma unroll
        for (int kk = 0; kk < 16; kk++) {
            float4 av0 = *(const float4*)&As[kk][ty * 8];
            float4 av1 = *(const float4*)&As[kk][ty * 8 + 4];
            float4 bv  = *(const float4*)&Bs[kk][tx * 4];
            float am[8] = {av0.x, av0.y, av0.z, av0.w, av1.x, av1.y, av1.z, av1.w};
            float bn[4] = {bv.x, bv.y, bv.z, bv.w};
#pragma unroll
            for (int i = 0; i < 8; i++)
#pragma unroll
                for (int j = 0; j < 4; j++)
                    acc[i][j] = fmaf(am[i], bn[j], acc[i][j]);
        }
    }
#pragma unroll
    for (int j = 0; j < 4; j++) {
        int n = tx * 4 + j;
        if (n < 48) {
#pragma unroll
            for (int i = 0; i < 8; i++)
                Cb[(size_t)n * NS + m0 + ty * 8 + i] = acc[i][j];
        }
    }
}

// ---------------------------------------------------------------------------
// conv: causal depthwise conv (4 taps) + SiLU; reads xz (b,s,1024) xh half,
// writes xc (b,d,s). Tile: 32 d x 128 s.
// ---------------------------------------------------------------------------
__global__ __launch_bounds__(256)
void conv_kernel(const float* __restrict__ xz, const float* __restrict__ cw,
                 const float* __restrict__ cb, float* __restrict__ xc) {
    __shared__ float sm[131 * 33];
    int b = blockIdx.z, d0 = blockIdx.y * 32, s0 = blockIdx.x * 128;
    int tid = threadIdx.x;
    for (int idx = tid; idx < 131 * 32; idx += 256) {
        int r = idx >> 5, c = idx & 31;
        int s = s0 - 3 + r;
        sm[r * 33 + c] =
            (s >= 0) ? xz[(size_t)(b * NS + s) * (2 * DI) + d0 + c] : 0.f;
    }
    __syncthreads();
    int dl = tid >> 3;          // 0..31
    int sl = (tid & 7) * 16;    // 0..112
    int d = d0 + dl;
    float w0 = cw[d * 4 + 0], w1 = cw[d * 4 + 1];
    float w2 = cw[d * 4 + 2], w3 = cw[d * 4 + 3];
    float bias = cb[d];
    float v[19];
#pragma unroll
    for (int j = 0; j < 19; j++) v[j] = sm[(sl + j) * 33 + dl];
    float o[16];
#pragma unroll
    for (int ss = 0; ss < 16; ss++) {
        float a = bias + w0 * v[ss] + w1 * v[ss + 1] + w2 * v[ss + 2] + w3 * v[ss + 3];
        o[ss] = a / (1.f + __expf(-a));
    }
    float* op = xc + (size_t)(b * DI + d) * NS + s0 + sl;
#pragma unroll
    for (int q = 0; q < 4; q++)
        *(float4*)(op + q * 4) = make_float4(o[q*4], o[q*4+1], o[q*4+2], o[q*4+3]);
}

// ---------------------------------------------------------------------------
// z transpose + SiLU: zt[b,d,s] = silu(xz[b,s,512+d])
// ---------------------------------------------------------------------------
__global__ __launch_bounds__(256)
void ztrans_kernel(const float* __restrict__ xz, float* __restrict__ zt) {
    __shared__ float sm[32][33];
    int b = blockIdx.z, d0 = blockIdx.y * 32, s0 = blockIdx.x * 32;
    int tx = threadIdx.x & 31, ty = threadIdx.x >> 5;  // ty 0..7
    for (int r = ty; r < 32; r += 8) {
        float z = xz[(size_t)(b * NS + s0 + r) * (2 * DI) + DI + d0 + tx];
        sm[r][tx] = z / (1.f + __expf(-z));
    }
    __syncthreads();
    for (int r = ty; r < 32; r += 8)
        zt[(size_t)(b * DI + d0 + r) * NS + s0 + tx] = sm[tx][r];
}

// ---------------------------------------------------------------------------
// dtproj: dt(b,d,s) = softplus( dtW(512,16) @ dtpre(16,s) + dtb ).
// Tile: 64 d x 128 s, K=16 in one pass.
// ---------------------------------------------------------------------------
__device__ __forceinline__ float softplus_f(float x) {
    return (x > 20.f) ? x : log1pf(__expf(x));
}

__global__ __launch_bounds__(256)
void dtproj_kernel(const float* __restrict__ dblt, const float* __restrict__ W,
                   const float* __restrict__ bias, float* __restrict__ dt) {
    __shared__ float Ws[16][64];
    __shared__ float Ps[16][128];
    int b = blockIdx.z, d0 = blockIdx.y * 64, s0 = blockIdx.x * 128;
    int tid = threadIdx.x;
    {
        int dl = tid >> 2, k4 = (tid & 3) * 4;
        float4 wv = *(const float4*)(W + (size_t)(d0 + dl) * 16 + k4);
        Ws[k4 + 0][dl] = wv.x; Ws[k4 + 1][dl] = wv.y;
        Ws[k4 + 2][dl] = wv.z; Ws[k4 + 3][dl] = wv.w;
    }
    const float* P = dblt + (size_t)b * 48 * NS;
#pragma unroll
    for (int it = 0; it < 2; it++) {
        int lin = tid + it * 256;
        int r = lin >> 5, c4 = (lin & 31) * 4;
        *(float4*)&Ps[r][c4] = *(const float4*)(P + (size_t)r * NS + s0 + c4);
    }
    __syncthreads();
    int ty = tid >> 4, tx = tid & 15;
    float acc[4][8];
#pragma unroll
    for (int i = 0; i < 4; i++)
#pragma unroll
        for (int j = 0; j < 8; j++) acc[i][j] = 0.f;
#pragma unroll
    for (int r = 0; r < 16; r++) {
        float4 a4 = *(const float4*)&Ws[r][ty * 4];
        float4 p0 = *(const float4*)&Ps[r][tx * 8];
        float4 p1 = *(const float4*)&Ps[r][tx * 8 + 4];
        float am[4] = {a4.x, a4.y, a4.z, a4.w};
        float pn[8] = {p0.x, p0.y, p0.z, p0.w, p1.x, p1.y, p1.z, p1.w};
#pragma unroll
        for (int i = 0; i < 4; i++)
#pragma unroll
            for (int j = 0; j < 8; j++)
                acc[i][j] = fmaf(am[i], pn[j], acc[i][j]);
    }
#pragma unroll
    for (int i = 0; i < 4; i++) {
        int dv = d0 + ty * 4 + i;
        float bi = bias[dv];
        float o[8];
#pragma unroll
        for (int j = 0; j < 8; j++) o[j] = softplus_f(acc[i][j] + bi);
        float* op = dt + (size_t)(b * DI + dv) * NS + s0 + tx * 8;
        *(float4*)(op)     = make_float4(o[0], o[1], o[2], o[3]);
        *(float4*)(op + 4) = make_float4(o[4], o[5], o[6], o[7]);
    }
}

// ---------------------------------------------------------------------------
// scan: lane = (dl<<4)|n handles state n of channel d. 16-lane groups.
// y[b,d,t] = (sum_n h_t[n]*C_t[n] + D*x_t) * silu(z_t)
// with h_t = exp(dt*A)*h_{t-1} + dt*x*B.
// ---------------------------------------------------------------------------
__global__ __launch_bounds__(128)
void scan_kernel(const float* __restrict__ dtp, const float* __restrict__ xcp,
                 const float* __restrict__ ztp, const float* __restrict__ dblt,
                 const float* __restrict__ Alog, const float* __restrict__ Dp,
                 float* __restrict__ yout) {
    int b = blockIdx.y;
    int warp = threadIdx.x >> 5, lane = threadIdx.x & 31;
    int dl = lane >> 4, n = lane & 15;
    int d = blockIdx.x * 8 + warp * 2 + dl;
    const float* dtr = dtp + (size_t)(b * DI + d) * NS;
    const float* xr  = xcp + (size_t)(b * DI + d) * NS;
    const float* zr  = ztp + (size_t)(b * DI + d) * NS;
    const float* Br  = dblt + (size_t)b * 48 * NS + (size_t)(16 + n) * NS;
    const float* Cr  = dblt + (size_t)b * 48 * NS + (size_t)(32 + n) * NS;
    float* yr = yout + (size_t)(b * DI + d) * NS;
    float a  = -__expf(Alog[d * DSTATE + n]);
    float Dv = Dp[d];
    float hst = 0.f;
    float4 dt4 = *(const float4*)dtr;
    float4 x4  = *(const float4*)xr;
    float4 z4  = *(const float4*)zr;
    float4 B4  = *(const float4*)Br;
    float4 C4  = *(const float4*)Cr;
    for (int t = 0; t < NS; t += 4) {
        float4 ndt = dt4, nx = x4, nz = z4, nB = B4, nC = C4;
        int t2 = t + 4;
        if (t2 < NS) {
            ndt = *(const float4*)(dtr + t2);
            nx  = *(const float4*)(xr + t2);
            nz  = *(const float4*)(zr + t2);
            nB  = *(const float4*)(Br + t2);
            nC  = *(const float4*)(Cr + t2);
        }
        float yo[4];
#pragma unroll
        for (int j = 0; j < 4; j++) {
            float dtv = (&dt4.x)[j], xv = (&x4.x)[j], zv = (&z4.x)[j];
            float Bv = (&B4.x)[j], Cv = (&C4.x)[j];
            float dA = __expf(dtv * a);
            hst = fmaf(dA, hst, dtv * xv * Bv);
            float p = hst * Cv;
            p += __shfl_xor_sync(0xffffffffu, p, 1);
            p += __shfl_xor_sync(0xffffffffu, p, 2);
            p += __shfl_xor_sync(0xffffffffu, p, 4);
            p += __shfl_xor_sync(0xffffffffu, p, 8);
            yo[j] = fmaf(Dv, xv, p) * zv;
        }
        if (n == 0)
            *(float4*)(yr + t) = make_float4(yo[0], yo[1], yo[2], yo[3]);
        dt4 = ndt; x4 = nx; z4 = nz; B4 = nB; C4 = nC;
    }
}

// ---------------------------------------------------------------------------
// head: out[row] = dot(h[row,:], out_W[:256]); warp per row
// ---------------------------------------------------------------------------
__global__ __launch_bounds__(256)
void head_kernel(const float* __restrict__ hin, const float* __restrict__ w,
                 float* __restrict__ out) {
    int wid = threadIdx.x >> 5, lane = threadIdx.x & 31;
    int row = blockIdx.x * 8 + wid;
    const float* hp = hin + (size_t)row * DM;
    int c0 = lane * 4, c1 = 128 + lane * 4;
    float4 v0 = *(const float4*)(hp + c0);
    float4 v1 = *(const float4*)(hp + c1);
    float4 w0 = *(const float4*)(w + c0);
    float4 w1 = *(const float4*)(w + c1);
    float s = v0.x*w0.x + v0.y*w0.y + v0.z*w0.z + v0.w*w0.w +
              v1.x*w1.x + v1.y*w1.y + v1.z*w1.z + v1.w*w1.w;
#pragma unroll
    for (int o = 16; o > 0; o >>= 1) s += __shfl_xor_sync(0xffffffffu, s, o);
    if (lane == 0) out[row] = s;
}

// ---------------------------------------------------------------------------
// host
// ---------------------------------------------------------------------------
extern "C" void kernel_launch(void* const* d_in, const int* in_sizes, int n_in,
                              void* d_out, int out_size) {
    const float* x_src     = (const float*)d_in[0];
    // d_in[1]: single_eval_pos (unused by reference math)
    const float* in_W      = (const float*)d_in[2];
    const float* norm_w    = (const float*)d_in[3];
    const float* norm_b    = (const float*)d_in[4];
    const float* inproj_W  = (const float*)d_in[5];
    const float* conv_w    = (const float*)d_in[6];
    const float* conv_b    = (const float*)d_in[7];
    const float* xproj_W   = (const float*)d_in[8];
    const float* dtproj_W  = (const float*)d_in[9];
    const float* dtproj_b  = (const float*)d_in[10];
    const float* A_log     = (const float*)d_in[11];
    const float* D_param   = (const float*)d_in[12];
    const float* outproj_W = (const float*)d_in[13];
    const float* out_W     = (const float*)d_in[14];
    float* out = (float*)d_out;

    float *ph, *pres, *phn, *pxz, *pxc, *pzt, *pdblt, *pdt, *py;
    cudaGetSymbolAddress((void**)&ph,    g_h);
    cudaGetSymbolAddress((void**)&pres,  g_res);
    cudaGetSymbolAddress((void**)&phn,   g_hn);
    cudaGetSymbolAddress((void**)&pxz,   g_xz);
    cudaGetSymbolAddress((void**)&pxc,   g_xc);
    cudaGetSymbolAddress((void**)&pzt,   g_zt);
    cudaGetSymbolAddress((void**)&pdblt, g_dblt);
    cudaGetSymbolAddress((void**)&pdt,   g_dt);
    cudaGetSymbolAddress((void**)&py,    g_y);

    embed_kernel<<<NTOK, 256>>>(x_src, in_W, ph);

    for (int l = 0; l < 4; l++) {
        ln_kernel<<<NTOK / 8, 256>>>(ph, pres, phn,
                                     norm_w + l * DM, norm_b + l * DM,
                                     (l == 0) ? 1 : 0);
        // inproj: (8192 x 1024) = hn(8192x256) * W(1024x256)^T
        {
            dim3 grid(1024 / 64, NTOK / 128);
            gemm_nt<<<grid, 256>>>(phn, inproj_W + (size_t)l * 1024 * DM, pxz,
                                   NTOK, 1024, DM);
        }
        conv_kernel<<<dim3(NS / 128, DI / 32, NB), 256>>>(
            pxz, conv_w + (size_t)l * DI * 4, conv_b + (size_t)l * DI, pxc);
        ztrans_kernel<<<dim3(NS / 32, DI / 32, NB), 256>>>(pxz, pzt);
        // xproj: per b, dblt(j=48, s=2048) from xc(512,2048)
        xproj_kernel<<<dim3(1, NS / 128, NB), 256>>>(
            pxc, xproj_W + (size_t)l * 48 * DI, pdblt);
        dtproj_kernel<<<dim3(NS / 128, DI / 64, NB), 256>>>(
            pdblt, dtproj_W + (size_t)l * DI * 16, dtproj_b + (size_t)l * DI, pdt);
        scan_kernel<<<dim3(DI / 8, NB), 128>>>(
            pdt, pxc, pzt, pdblt,
            A_log + (size_t)l * DI * DSTATE, D_param + (size_t)l * DI, py);
        // outproj: per b, h(2048x256) = y^T(2048x512) * W(256x512)^T
        gemm_tn<<<dim3(DM / 64, NS / 128, NB), 256>>>(
            py, outproj_W + (size_t)l * DM * DI, ph,
            NS, DM, DI, (size_t)DI * NS, (size_t)NS * DM);
    }

    head_kernel<<<NTOK / 8, 256>>>(ph, out_W, out);
}

// round 5
// speedup vs baseline: 1.3468x; 1.3468x over previous
#include <cuda_runtime.h>
#include <cuda_bf16.h>
#include <cstdint>
#include <cstddef>

// ---------------------------------------------------------------------------
// Mamba model. GEMMs on tensor cores (tf32 mma.sync), scan in fp32 SIMT.
// Shapes: B=4, S=2048, D_MODEL=256, D_INNER=512, D_STATE=16, DT_RANK=16.
// Layouts: h/res/hn/xz (b,s,feature) row-major; xc/zt/dt/y TRANSPOSED (b,d,s);
//          dblt (b,j,s), j: 0..15 dt_pre, 16..31 B, 32..47 C.
// ---------------------------------------------------------------------------

#define NB     4
#define NS     2048
#define DM     256
#define DI     512
#define DSTATE 16
#define NTOK   (NB * NS)          // 8192

__device__ float g_h   [NTOK * DM];
__device__ float g_res [NTOK * DM];
__device__ float g_hn  [NTOK * DM];
__device__ float g_xz  [NTOK * 2 * DI];
__device__ float g_xc  [NB * DI * NS];
__device__ float g_zt  [NB * DI * NS];
__device__ float g_dblt[NB * 48 * NS];
__device__ float g_dt  [NB * DI * NS];
__device__ float g_y   [NB * DI * NS];

// ---------------------------------------------------------------------------
// tf32 helpers
// ---------------------------------------------------------------------------
__device__ __forceinline__ uint32_t f2tf(float x) {
    uint32_t u;
    asm("cvt.rna.tf32.f32 %0, %1;" : "=r"(u) : "f"(x));
    return u;
}

__device__ __forceinline__ void mma_tf32(float* c, const uint32_t* a,
                                         uint32_t b0, uint32_t b1) {
    asm volatile(
        "mma.sync.aligned.m16n8k8.row.col.f32.tf32.tf32.f32 "
        "{%0,%1,%2,%3},{%4,%5,%6,%7},{%8,%9},{%0,%1,%2,%3};"
        : "+f"(c[0]), "+f"(c[1]), "+f"(c[2]), "+f"(c[3])
        : "r"(a[0]), "r"(a[1]), "r"(a[2]), "r"(a[3]), "r"(b0), "r"(b1));
}

// ---------------------------------------------------------------------------
// embed
// ---------------------------------------------------------------------------
__global__ __launch_bounds__(256)
void embed_kernel(const float* __restrict__ x, const float* __restrict__ W,
                  float* __restrict__ h) {
    __shared__ float xs[15];
    int row = blockIdx.x;
    if (threadIdx.x < 15) xs[threadIdx.x] = x[row * 15 + threadIdx.x];
    __syncthreads();
    int m = threadIdx.x;
    const float* wr = W + m * 15;
    float acc = 0.f;
#pragma unroll
    for (int k = 0; k < 15; k++) acc = fmaf(xs[k], wr[k], acc);
    h[(size_t)row * DM + m] = acc;
}

// ---------------------------------------------------------------------------
// fused residual + layernorm; one warp per row of 256
// ---------------------------------------------------------------------------
__global__ __launch_bounds__(256)
void ln_kernel(const float* __restrict__ hin, float* __restrict__ res,
               float* __restrict__ hn, const float* __restrict__ w,
               const float* __restrict__ bb, int first) {
    int wid = threadIdx.x >> 5, lane = threadIdx.x & 31;
    int row = blockIdx.x * 8 + wid;
    const float* hp = hin + (size_t)row * DM;
    float* rp = res + (size_t)row * DM;
    float* op = hn + (size_t)row * DM;
    int c0 = lane * 4, c1 = 128 + lane * 4;
    float4 v0 = *(const float4*)(hp + c0);
    float4 v1 = *(const float4*)(hp + c1);
    if (!first) {
        float4 r0 = *(const float4*)(rp + c0);
        float4 r1 = *(const float4*)(rp + c1);
        v0.x += r0.x; v0.y += r0.y; v0.z += r0.z; v0.w += r0.w;
        v1.x += r1.x; v1.y += r1.y; v1.z += r1.z; v1.w += r1.w;
    }
    *(float4*)(rp + c0) = v0;
    *(float4*)(rp + c1) = v1;
    float s = v0.x + v0.y + v0.z + v0.w + v1.x + v1.y + v1.z + v1.w;
    float q = v0.x*v0.x + v0.y*v0.y + v0.z*v0.z + v0.w*v0.w +
              v1.x*v1.x + v1.y*v1.y + v1.z*v1.z + v1.w*v1.w;
#pragma unroll
    for (int o = 16; o > 0; o >>= 1) {
        s += __shfl_xor_sync(0xffffffffu, s, o);
        q += __shfl_xor_sync(0xffffffffu, q, o);
    }
    float m  = s * (1.f / 256.f);
    float var = q * (1.f / 256.f) - m * m;
    float rstd = rsqrtf(var + 1e-5f);
    float4 w0 = *(const float4*)(w + c0), w1 = *(const float4*)(w + c1);
    float4 b0 = *(const float4*)(bb + c0), b1 = *(const float4*)(bb + c1);
    float4 o0, o1;
    o0.x = (v0.x - m) * rstd * w0.x + b0.x;
    o0.y = (v0.y - m) * rstd * w0.y + b0.y;
    o0.z = (v0.z - m) * rstd * w0.z + b0.z;
    o0.w = (v0.w - m) * rstd * w0.w + b0.w;
    o1.x = (v1.x - m) * rstd * w1.x + b1.x;
    o1.y = (v1.y - m) * rstd * w1.y + b1.y;
    o1.z = (v1.z - m) * rstd * w1.z + b1.z;
    o1.w = (v1.w - m) * rstd * w1.w + b1.w;
    *(float4*)(op + c0) = o0;
    *(float4*)(op + c1) = o1;
}

// ---------------------------------------------------------------------------
// tc_nt: C[M,N] = A(M,K) * B(N,K)^T via tf32 mma. Block 128x64, ktile 32.
// 8 warps as 4(m) x 2(n); warp tile 32x32 = 2 m16 x 4 n8.
// Used for inproj: A=hn(8192,256), B=inproj_W(1024,256), C=xz.
// ---------------------------------------------------------------------------
__global__ __launch_bounds__(256)
void tc_nt(const float* __restrict__ A, const float* __restrict__ B,
           float* __restrict__ C, int M, int N, int K) {
    __shared__ uint32_t As[128][36];
    __shared__ uint32_t Bs[64][36];
    int tid = threadIdx.x;
    int m0 = blockIdx.y * 128, n0 = blockIdx.x * 64;
    int lane = tid & 31, wid = tid >> 5;
    int wm = (wid >> 1) * 32, wn = (wid & 1) * 32;
    int gr = lane >> 2, gc = lane & 3;
    float acc[2][4][4];
#pragma unroll
    for (int i = 0; i < 2; i++)
#pragma unroll
        for (int j = 0; j < 4; j++)
#pragma unroll
            for (int q = 0; q < 4; q++) acc[i][j][q] = 0.f;
    int lrow = tid >> 3;        // 0..31
    int lc4  = (tid & 7) * 4;   // 0..28
    const float* Ap = A + (size_t)(m0 + lrow) * K + lc4;
    const float* Bp = B + (size_t)(n0 + lrow) * K + lc4;

    for (int k0 = 0; k0 < K; k0 += 32) {
        float4 av[4], bv[2];
#pragma unroll
        for (int i = 0; i < 4; i++)
            av[i] = *(const float4*)(Ap + (size_t)(i * 32) * K + k0);
#pragma unroll
        for (int i = 0; i < 2; i++)
            bv[i] = *(const float4*)(Bp + (size_t)(i * 32) * K + k0);
        __syncthreads();
#pragma unroll
        for (int i = 0; i < 4; i++) {
            uint4 u;
            u.x = f2tf(av[i].x); u.y = f2tf(av[i].y);
            u.z = f2tf(av[i].z); u.w = f2tf(av[i].w);
            *(uint4*)&As[lrow + i * 32][lc4] = u;
        }
#pragma unroll
        for (int i = 0; i < 2; i++) {
            uint4 u;
            u.x = f2tf(bv[i].x); u.y = f2tf(bv[i].y);
            u.z = f2tf(bv[i].z); u.w = f2tf(bv[i].w);
            *(uint4*)&Bs[lrow + i * 32][lc4] = u;
        }
        __syncthreads();
#pragma unroll
        for (int ks = 0; ks < 4; ks++) {
            int kb = ks * 8;
            uint32_t a[2][4];
#pragma unroll
            for (int mi = 0; mi < 2; mi++) {
                int rb = wm + mi * 16 + gr;
                a[mi][0] = As[rb    ][kb + gc];
                a[mi][1] = As[rb + 8][kb + gc];
                a[mi][2] = As[rb    ][kb + gc + 4];
                a[mi][3] = As[rb + 8][kb + gc + 4];
            }
#pragma unroll
            for (int ni = 0; ni < 4; ni++) {
                uint32_t b0 = Bs[wn + ni * 8 + gr][kb + gc];
                uint32_t b1 = Bs[wn + ni * 8 + gr][kb + gc + 4];
#pragma unroll
                for (int mi = 0; mi < 2; mi++)
                    mma_tf32(acc[mi][ni], a[mi], b0, b1);
            }
        }
    }
#pragma unroll
    for (int mi = 0; mi < 2; mi++) {
        int r0 = m0 + wm + mi * 16 + gr;
#pragma unroll
        for (int ni = 0; ni < 4; ni++) {
            int cc = n0 + wn + ni * 8 + 2 * gc;
            *(float2*)(C + (size_t)r0 * N + cc) =
                make_float2(acc[mi][ni][0], acc[mi][ni][1]);
            *(float2*)(C + (size_t)(r0 + 8) * N + cc) =
                make_float2(acc[mi][ni][2], acc[mi][ni][3]);
        }
    }
}

// ---------------------------------------------------------------------------
// tc_op (outproj): per batch, C'(dm=256, s=2048) = W(256,512) x y(d,s).
// y is k-major (d rows, s contiguous) -> native B "col" fragment.
// Epilogue scatters C' into h (b,s,dm) row-major (full 32B sectors).
// Block 128(dm) x 64(s), ktile 32. Warps 4(m) x 2(n).
// ---------------------------------------------------------------------------
__global__ __launch_bounds__(256)
void tc_op(const float* __restrict__ W, const float* __restrict__ Y,
           float* __restrict__ H) {
    __shared__ uint32_t As[128][36];
    __shared__ uint32_t Bs[32][72];
    int b = blockIdx.z;
    int m0 = blockIdx.y * 128, s0 = blockIdx.x * 64;
    const float* Yb = Y + (size_t)b * DI * NS;
    int tid = threadIdx.x, lane = tid & 31, wid = tid >> 5;
    int wm = (wid >> 1) * 32, wn = (wid & 1) * 32;
    int gr = lane >> 2, gc = lane & 3;
    float acc[2][4][4];
#pragma unroll
    for (int i = 0; i < 2; i++)
#pragma unroll
        for (int j = 0; j < 4; j++)
#pragma unroll
            for (int q = 0; q < 4; q++) acc[i][j][q] = 0.f;
    int lrow = tid >> 3, lc4 = (tid & 7) * 4;   // A map
    int bk = tid >> 4, bn4 = (tid & 15) * 4;    // B map
    const float* Ap = W + (size_t)(m0 + lrow) * DI + lc4;

    for (int k0 = 0; k0 < DI; k0 += 32) {
        float4 av[4], bv[2];
#pragma unroll
        for (int i = 0; i < 4; i++)
            av[i] = *(const float4*)(Ap + (size_t)(i * 32) * DI + k0);
#pragma unroll
        for (int i = 0; i < 2; i++)
            bv[i] = *(const float4*)(Yb + (size_t)(k0 + bk + i * 16) * NS + s0 + bn4);
        __syncthreads();
#pragma unroll
        for (int i = 0; i < 4; i++) {
            uint4 u;
            u.x = f2tf(av[i].x); u.y = f2tf(av[i].y);
            u.z = f2tf(av[i].z); u.w = f2tf(av[i].w);
            *(uint4*)&As[lrow + i * 32][lc4] = u;
        }
#pragma unroll
        for (int i = 0; i < 2; i++) {
            uint4 u;
            u.x = f2tf(bv[i].x); u.y = f2tf(bv[i].y);
            u.z = f2tf(bv[i].z); u.w = f2tf(bv[i].w);
            *(uint4*)&Bs[bk + i * 16][bn4] = u;
        }
        __syncthreads();
#pragma unroll
        for (int ks = 0; ks < 4; ks++) {
            int kb = ks * 8;
            uint32_t a[2][4];
#pragma unroll
            for (int mi = 0; mi < 2; mi++) {
                int rb = wm + mi * 16 + gr;
                a[mi][0] = As[rb    ][kb + gc];
                a[mi][1] = As[rb + 8][kb + gc];
                a[mi][2] = As[rb    ][kb + gc + 4];
                a[mi][3] = As[rb + 8][kb + gc + 4];
            }
#pragma unroll
            for (int ni = 0; ni < 4; ni++) {
                int nn = wn + ni * 8 + gr;
                uint32_t b0 = Bs[kb + gc    ][nn];
                uint32_t b1 = Bs[kb + gc + 4][nn];
#pragma unroll
                for (int mi = 0; mi < 2; mi++)
                    mma_tf32(acc[mi][ni], a[mi], b0, b1);
            }
        }
    }
    // scatter epilogue: H[(b*NS + s)*DM + dm]
#pragma unroll
    for (int mi = 0; mi < 2; mi++) {
        int dm = m0 + wm + mi * 16 + gr;
#pragma unroll
        for (int ni = 0; ni < 4; ni++) {
            int s = s0 + wn + ni * 8 + 2 * gc;
            size_t r0 = (size_t)(b * NS + s) * DM;
            size_t r1 = (size_t)(b * NS + s + 1) * DM;
            H[r0 + dm]     = acc[mi][ni][0];
            H[r1 + dm]     = acc[mi][ni][1];
            H[r0 + dm + 8] = acc[mi][ni][2];
            H[r1 + dm + 8] = acc[mi][ni][3];
        }
    }
}

// ---------------------------------------------------------------------------
// tc_xp (xproj): per batch, dblt(j=48, s) = xpW(48,512) x xc(d,s).
// Block 64(m, 48 valid) x 64(s), ktile 32. Warps 2(m) x 4(n);
// warp tile 32(m) x 16(n) = 2 m16 x 2 n8. Row-major epilogue (native!).
// ---------------------------------------------------------------------------
__global__ __launch_bounds__(256)
void tc_xp(const float* __restrict__ W, const float* __restrict__ X,
           float* __restrict__ Dt) {
    __shared__ uint32_t As[64][36];
    __shared__ uint32_t Bs[32][72];
    int b = blockIdx.z;
    int s0 = blockIdx.x * 64;
    const float* Xb = X + (size_t)b * DI * NS;
    float* Db = Dt + (size_t)b * 48 * NS;
    int tid = threadIdx.x, lane = tid & 31, wid = tid >> 5;
    int wm = (wid >> 2) * 32, wn = (wid & 3) * 16;
    int gr = lane >> 2, gc = lane & 3;
    float acc[2][2][4];
#pragma unroll
    for (int i = 0; i < 2; i++)
#pragma unroll
        for (int j = 0; j < 2; j++)
#pragma unroll
            for (int q = 0; q < 4; q++) acc[i][j][q] = 0.f;
    int lrow = tid >> 3, lc4 = (tid & 7) * 4;
    int bk = tid >> 4, bn4 = (tid & 15) * 4;

    for (int k0 = 0; k0 < DI; k0 += 32) {
        float4 av[2], bv[2];
#pragma unroll
        for (int i = 0; i < 2; i++) {
            int r = lrow + i * 32;
            av[i] = (r < 48)
                ? *(const float4*)(W + (size_t)r * DI + k0 + lc4)
                : make_float4(0.f, 0.f, 0.f, 0.f);
        }
#pragma unroll
        for (int i = 0; i < 2; i++)
            bv[i] = *(const float4*)(Xb + (size_t)(k0 + bk + i * 16) * NS + s0 + bn4);
        __syncthreads();
#pragma unroll
        for (int i = 0; i < 2; i++) {
            uint4 u;
            u.x = f2tf(av[i].x); u.y = f2tf(av[i].y);
            u.z = f2tf(av[i].z); u.w = f2tf(av[i].w);
            *(uint4*)&As[lrow + i * 32][lc4] = u;
        }
#pragma unroll
        for (int i = 0; i < 2; i++) {
            uint4 u;
            u.x = f2tf(bv[i].x); u.y = f2tf(bv[i].y);
            u.z = f2tf(bv[i].z); u.w = f2tf(bv[i].w);
            *(uint4*)&Bs[bk + i * 16][bn4] = u;
        }
        __syncthreads();
#pragma unroll
        for (int ks = 0; ks < 4; ks++) {
            int kb = ks * 8;
            uint32_t a[2][4];
#pragma unroll
            for (int mi = 0; mi < 2; mi++) {
                int rb = wm + mi * 16 + gr;
                a[mi][0] = As[rb    ][kb + gc];
                a[mi][1] = As[rb + 8][kb + gc];
                a[mi][2] = As[rb    ][kb + gc + 4];
                a[mi][3] = As[rb + 8][kb + gc + 4];
            }
#pragma unroll
            for (int ni = 0; ni < 2; ni++) {
                int nn = wn + ni * 8 + gr;
                uint32_t b0 = Bs[kb + gc    ][nn];
                uint32_t b1 = Bs[kb + gc + 4][nn];
#pragma unroll
                for (int mi = 0; mi < 2; mi++)
                    mma_tf32(acc[mi][ni], a[mi], b0, b1);
            }
        }
    }
#pragma unroll
    for (int mi = 0; mi < 2; mi++) {
        int m = wm + mi * 16 + gr;
#pragma unroll
        for (int ni = 0; ni < 2; ni++) {
            int sc = s0 + wn + ni * 8 + 2 * gc;
            if (m < 48)
                *(float2*)(Db + (size_t)m * NS + sc) =
                    make_float2(acc[mi][ni][0], acc[mi][ni][1]);
            if (m + 8 < 48)
                *(float2*)(Db + (size_t)(m + 8) * NS + sc) =
                    make_float2(acc[mi][ni][2], acc[mi][ni][3]);
        }
    }
}

// ---------------------------------------------------------------------------
// conv: causal depthwise conv (4 taps) + SiLU; xz (b,s,1024) -> xc (b,d,s)
// ---------------------------------------------------------------------------
__global__ __launch_bounds__(256)
void conv_kernel(const float* __restrict__ xz, const float* __restrict__ cw,
                 const float* __restrict__ cb, float* __restrict__ xc) {
    __shared__ float sm[131 * 33];
    int b = blockIdx.z, d0 = blockIdx.y * 32, s0 = blockIdx.x * 128;
    int tid = threadIdx.x;
    for (int idx = tid; idx < 131 * 32; idx += 256) {
        int r = idx >> 5, c = idx & 31;
        int s = s0 - 3 + r;
        sm[r * 33 + c] =
            (s >= 0) ? xz[(size_t)(b * NS + s) * (2 * DI) + d0 + c] : 0.f;
    }
    __syncthreads();
    int dl = tid >> 3;
    int sl = (tid & 7) * 16;
    int d = d0 + dl;
    float w0 = cw[d * 4 + 0], w1 = cw[d * 4 + 1];
    float w2 = cw[d * 4 + 2], w3 = cw[d * 4 + 3];
    float bias = cb[d];
    float v[19];
#pragma unroll
    for (int j = 0; j < 19; j++) v[j] = sm[(sl + j) * 33 + dl];
    float o[16];
#pragma unroll
    for (int ss = 0; ss < 16; ss++) {
        float a = bias + w0 * v[ss] + w1 * v[ss + 1] + w2 * v[ss + 2] + w3 * v[ss + 3];
        o[ss] = a / (1.f + __expf(-a));
    }
    float* op = xc + (size_t)(b * DI + d) * NS + s0 + sl;
#pragma unroll
    for (int q = 0; q < 4; q++)
        *(float4*)(op + q * 4) = make_float4(o[q*4], o[q*4+1], o[q*4+2], o[q*4+3]);
}

// ---------------------------------------------------------------------------
// z transpose + SiLU
// ---------------------------------------------------------------------------
__global__ __launch_bounds__(256)
void ztrans_kernel(const float* __restrict__ xz, float* __restrict__ zt) {
    __shared__ float sm[32][33];
    int b = blockIdx.z, d0 = blockIdx.y * 32, s0 = blockIdx.x * 32;
    int tx = threadIdx.x & 31, ty = threadIdx.x >> 5;
    for (int r = ty; r < 32; r += 8) {
        float z = xz[(size_t)(b * NS + s0 + r) * (2 * DI) + DI + d0 + tx];
        sm[r][tx] = z / (1.f + __expf(-z));
    }
    __syncthreads();
    for (int r = ty; r < 32; r += 8)
        zt[(size_t)(b * DI + d0 + r) * NS + s0 + tx] = sm[tx][r];
}

// ---------------------------------------------------------------------------
// dtproj (fp32, cheap): dt(b,d,s) = softplus(dtW(512,16) @ dtpre(16,s) + dtb)
// ---------------------------------------------------------------------------
__device__ __forceinline__ float softplus_f(float x) {
    return (x > 20.f) ? x : log1pf(__expf(x));
}

__global__ __launch_bounds__(256)
void dtproj_kernel(const float* __restrict__ dblt, const float* __restrict__ W,
                   const float* __restrict__ bias, float* __restrict__ dt) {
    __shared__ float Ws[16][64];
    __shared__ float Ps[16][128];
    int b = blockIdx.z, d0 = blockIdx.y * 64, s0 = blockIdx.x * 128;
    int tid = threadIdx.x;
    {
        int dl = tid >> 2, k4 = (tid & 3) * 4;
        float4 wv = *(const float4*)(W + (size_t)(d0 + dl) * 16 + k4);
        Ws[k4 + 0][dl] = wv.x; Ws[k4 + 1][dl] = wv.y;
        Ws[k4 + 2][dl] = wv.z; Ws[k4 + 3][dl] = wv.w;
    }
    const float* P = dblt + (size_t)b * 48 * NS;
#pragma unroll
    for (int it = 0; it < 2; it++) {
        int lin = tid + it * 256;
        int r = lin >> 5, c4 = (lin & 31) * 4;
        *(float4*)&Ps[r][c4] = *(const float4*)(P + (size_t)r * NS + s0 + c4);
    }
    __syncthreads();
    int ty = tid >> 4, tx = tid & 15;
    float acc[4][8];
#pragma unroll
    for (int i = 0; i < 4; i++)
#pragma unroll
        for (int j = 0; j < 8; j++) acc[i][j] = 0.f;
#pragma unroll
    for (int r = 0; r < 16; r++) {
        float4 a4 = *(const float4*)&Ws[r][ty * 4];
        float4 p0 = *(const float4*)&Ps[r][tx * 8];
        float4 p1 = *(const float4*)&Ps[r][tx * 8 + 4];
        float am[4] = {a4.x, a4.y, a4.z, a4.w};
        float pn[8] = {p0.x, p0.y, p0.z, p0.w, p1.x, p1.y, p1.z, p1.w};
#pragma unroll
        for (int i = 0; i < 4; i++)
#pragma unroll
            for (int j = 0; j < 8; j++)
                acc[i][j] = fmaf(am[i], pn[j], acc[i][j]);
    }
#pragma unroll
    for (int i = 0; i < 4; i++) {
        int dv = d0 + ty * 4 + i;
        float bi = bias[dv];
        float o[8];
#pragma unroll
        for (int j = 0; j < 8; j++) o[j] = softplus_f(acc[i][j] + bi);
        float* op = dt + (size_t)(b * DI + dv) * NS + s0 + tx * 8;
        *(float4*)(op)     = make_float4(o[0], o[1], o[2], o[3]);
        *(float4*)(op + 4) = make_float4(o[4], o[5], o[6], o[7]);
    }
}

// ---------------------------------------------------------------------------
// scan (unchanged from R3)
// ---------------------------------------------------------------------------
__global__ __launch_bounds__(128)
void scan_kernel(const float* __restrict__ dtp, const float* __restrict__ xcp,
                 const float* __restrict__ ztp, const float* __restrict__ dblt,
                 const float* __restrict__ Alog, const float* __restrict__ Dp,
                 float* __restrict__ yout) {
    int b = blockIdx.y;
    int warp = threadIdx.x >> 5, lane = threadIdx.x & 31;
    int dl = lane >> 4, n = lane & 15;
    int d = blockIdx.x * 8 + warp * 2 + dl;
    const float* dtr = dtp + (size_t)(b * DI + d) * NS;
    const float* xr  = xcp + (size_t)(b * DI + d) * NS;
    const float* zr  = ztp + (size_t)(b * DI + d) * NS;
    const float* Br  = dblt + (size_t)b * 48 * NS + (size_t)(16 + n) * NS;
    const float* Cr  = dblt + (size_t)b * 48 * NS + (size_t)(32 + n) * NS;
    float* yr = yout + (size_t)(b * DI + d) * NS;
    float a  = -__expf(Alog[d * DSTATE + n]);
    float Dv = Dp[d];
    float hst = 0.f;
    float4 dt4 = *(const float4*)dtr;
    float4 x4  = *(const float4*)xr;
    float4 z4  = *(const float4*)zr;
    float4 B4  = *(const float4*)Br;
    float4 C4  = *(const float4*)Cr;
    for (int t = 0; t < NS; t += 4) {
        float4 ndt = dt4, nx = x4, nz = z4, nB = B4, nC = C4;
        int t2 = t + 4;
        if (t2 < NS) {
            ndt = *(const float4*)(dtr + t2);
            nx  = *(const float4*)(xr + t2);
            nz  = *(const float4*)(zr + t2);
            nB  = *(const float4*)(Br + t2);
            nC  = *(const float4*)(Cr + t2);
        }
        float yo[4];
#pragma unroll
        for (int j = 0; j < 4; j++) {
            float dtv = (&dt4.x)[j], xv = (&x4.x)[j], zv = (&z4.x)[j];
            float Bv = (&B4.x)[j], Cv = (&C4.x)[j];
            float dA = __expf(dtv * a);
            hst = fmaf(dA, hst, dtv * xv * Bv);
            float p = hst * Cv;
            p += __shfl_xor_sync(0xffffffffu, p, 1);
            p += __shfl_xor_sync(0xffffffffu, p, 2);
            p += __shfl_xor_sync(0xffffffffu, p, 4);
            p += __shfl_xor_sync(0xffffffffu, p, 8);
            yo[j] = fmaf(Dv, xv, p) * zv;
        }
        if (n == 0)
            *(float4*)(yr + t) = make_float4(yo[0], yo[1], yo[2], yo[3]);
        dt4 = ndt; x4 = nx; z4 = nz; B4 = nB; C4 = nC;
    }
}

// ---------------------------------------------------------------------------
// head
// ---------------------------------------------------------------------------
__global__ __launch_bounds__(256)
void head_kernel(const float* __restrict__ hin, const float* __restrict__ w,
                 float* __restrict__ out) {
    int wid = threadIdx.x >> 5, lane = threadIdx.x & 31;
    int row = blockIdx.x * 8 + wid;
    const float* hp = hin + (size_t)row * DM;
    int c0 = lane * 4, c1 = 128 + lane * 4;
    float4 v0 = *(const float4*)(hp + c0);
    float4 v1 = *(const float4*)(hp + c1);
    float4 w0 = *(const float4*)(w + c0);
    float4 w1 = *(const float4*)(w + c1);
    float s = v0.x*w0.x + v0.y*w0.y + v0.z*w0.z + v0.w*w0.w +
              v1.x*w1.x + v1.y*w1.y + v1.z*w1.z + v1.w*w1.w;
#pragma unroll
    for (int o = 16; o > 0; o >>= 1) s += __shfl_xor_sync(0xffffffffu, s, o);
    if (lane == 0) out[row] = s;
}

// ---------------------------------------------------------------------------
// host
// ---------------------------------------------------------------------------
extern "C" void kernel_launch(void* const* d_in, const int* in_sizes, int n_in,
                              void* d_out, int out_size) {
    const float* x_src     = (const float*)d_in[0];
    const float* in_W      = (const float*)d_in[2];
    const float* norm_w    = (const float*)d_in[3];
    const float* norm_b    = (const float*)d_in[4];
    const float* inproj_W  = (const float*)d_in[5];
    const float* conv_w    = (const float*)d_in[6];
    const float* conv_b    = (const float*)d_in[7];
    const float* xproj_W   = (const float*)d_in[8];
    const float* dtproj_W  = (const float*)d_in[9];
    const float* dtproj_b  = (const float*)d_in[10];
    const float* A_log     = (const float*)d_in[11];
    const float* D_param   = (const float*)d_in[12];
    const float* outproj_W = (const float*)d_in[13];
    const float* out_W     = (const float*)d_in[14];
    float* out = (float*)d_out;

    float *ph, *pres, *phn, *pxz, *pxc, *pzt, *pdblt, *pdt, *py;
    cudaGetSymbolAddress((void**)&ph,    g_h);
    cudaGetSymbolAddress((void**)&pres,  g_res);
    cudaGetSymbolAddress((void**)&phn,   g_hn);
    cudaGetSymbolAddress((void**)&pxz,   g_xz);
    cudaGetSymbolAddress((void**)&pxc,   g_xc);
    cudaGetSymbolAddress((void**)&pzt,   g_zt);
    cudaGetSymbolAddress((void**)&pdblt, g_dblt);
    cudaGetSymbolAddress((void**)&pdt,   g_dt);
    cudaGetSymbolAddress((void**)&py,    g_y);

    embed_kernel<<<NTOK, 256>>>(x_src, in_W, ph);

    for (int l = 0; l < 4; l++) {
        ln_kernel<<<NTOK / 8, 256>>>(ph, pres, phn,
                                     norm_w + l * DM, norm_b + l * DM,
                                     (l == 0) ? 1 : 0);
        // inproj: xz(8192,1024) = hn(8192,256) * W(1024,256)^T  [tensor cores]
        tc_nt<<<dim3(1024 / 64, NTOK / 128), 256>>>(
            phn, inproj_W + (size_t)l * 1024 * DM, pxz, NTOK, 1024, DM);
        conv_kernel<<<dim3(NS / 128, DI / 32, NB), 256>>>(
            pxz, conv_w + (size_t)l * DI * 4, conv_b + (size_t)l * DI, pxc);
        ztrans_kernel<<<dim3(NS / 32, DI / 32, NB), 256>>>(pxz, pzt);
        // xproj: dblt(48, s) = xpW(48,512) * xc(d, s)  [tensor cores]
        tc_xp<<<dim3(NS / 64, 1, NB), 256>>>(
            xproj_W + (size_t)l * 48 * DI, pxc, pdblt);
        dtproj_kernel<<<dim3(NS / 128, DI / 64, NB), 256>>>(
            pdblt, dtproj_W + (size_t)l * DI * 16, dtproj_b + (size_t)l * DI, pdt);
        scan_kernel<<<dim3(DI / 8, NB), 128>>>(
            pdt, pxc, pzt, pdblt,
            A_log + (size_t)l * DI * DSTATE, D_param + (size_t)l * DI, py);
        // outproj: h(s,dm) <- W(256,512) * y(d,s)  [tensor cores, scatter epi]
        tc_op<<<dim3(NS / 64, DM / 128, NB), 256>>>(
            outproj_W + (size_t)l * DM * DI, py, ph);
    }

    head_kernel<<<NTOK / 8, 256>>>(ph, out_W, out);
}

// round 6
// speedup vs baseline: 1.3714x; 1.0183x over previous
#include <cuda_runtime.h>
#include <cuda_bf16.h>
#include <cstdint>
#include <cstddef>

// ---------------------------------------------------------------------------
// Mamba model. GEMMs: double-buffered tf32 mma.sync pipelines. Scan fp32 SIMT.
// Layouts: h/res/hn/xz (b,s,feature) row-major; xc/zt/dt/y TRANSPOSED (b,d,s);
//          dblt (b,j,s), j: 0..15 dt_pre, 16..31 B, 32..47 C.
// ---------------------------------------------------------------------------

#define NB     4
#define NS     2048
#define DM     256
#define DI     512
#define DSTATE 16
#define NTOK   (NB * NS)

__device__ float g_h   [NTOK * DM];
__device__ float g_res [NTOK * DM];
__device__ float g_hn  [NTOK * DM];
__device__ float g_xz  [NTOK * 2 * DI];
__device__ float g_xc  [NB * DI * NS];
__device__ float g_zt  [NB * DI * NS];
__device__ float g_dblt[NB * 48 * NS];
__device__ float g_dt  [NB * DI * NS];
__device__ float g_y   [NB * DI * NS];

// ---------------------------------------------------------------------------
__device__ __forceinline__ uint32_t f2tf(float x) {
    uint32_t u;
    asm("cvt.rna.tf32.f32 %0, %1;" : "=r"(u) : "f"(x));
    return u;
}

__device__ __forceinline__ void mma_tf32(float* c, const uint32_t* a,
                                         uint32_t b0, uint32_t b1) {
    asm volatile(
        "mma.sync.aligned.m16n8k8.row.col.f32.tf32.tf32.f32 "
        "{%0,%1,%2,%3},{%4,%5,%6,%7},{%8,%9},{%0,%1,%2,%3};"
        : "+f"(c[0]), "+f"(c[1]), "+f"(c[2]), "+f"(c[3])
        : "r"(a[0]), "r"(a[1]), "r"(a[2]), "r"(a[3]), "r"(b0), "r"(b1));
}

__device__ __forceinline__ uint4 cvt4(float4 v) {
    uint4 u;
    u.x = f2tf(v.x); u.y = f2tf(v.y); u.z = f2tf(v.z); u.w = f2tf(v.w);
    return u;
}

// ---------------------------------------------------------------------------
// embed
// ---------------------------------------------------------------------------
__global__ __launch_bounds__(256)
void embed_kernel(const float* __restrict__ x, const float* __restrict__ W,
                  float* __restrict__ h) {
    __shared__ float xs[15];
    int row = blockIdx.x;
    if (threadIdx.x < 15) xs[threadIdx.x] = x[row * 15 + threadIdx.x];
    __syncthreads();
    int m = threadIdx.x;
    const float* wr = W + m * 15;
    float acc = 0.f;
#pragma unroll
    for (int k = 0; k < 15; k++) acc = fmaf(xs[k], wr[k], acc);
    h[(size_t)row * DM + m] = acc;
}

// ---------------------------------------------------------------------------
// fused residual + layernorm; one warp per row of 256
// ---------------------------------------------------------------------------
__global__ __launch_bounds__(256)
void ln_kernel(const float* __restrict__ hin, float* __restrict__ res,
               float* __restrict__ hn, const float* __restrict__ w,
               const float* __restrict__ bb, int first) {
    int wid = threadIdx.x >> 5, lane = threadIdx.x & 31;
    int row = blockIdx.x * 8 + wid;
    const float* hp = hin + (size_t)row * DM;
    float* rp = res + (size_t)row * DM;
    float* op = hn + (size_t)row * DM;
    int c0 = lane * 4, c1 = 128 + lane * 4;
    float4 v0 = *(const float4*)(hp + c0);
    float4 v1 = *(const float4*)(hp + c1);
    if (!first) {
        float4 r0 = *(const float4*)(rp + c0);
        float4 r1 = *(const float4*)(rp + c1);
        v0.x += r0.x; v0.y += r0.y; v0.z += r0.z; v0.w += r0.w;
        v1.x += r1.x; v1.y += r1.y; v1.z += r1.z; v1.w += r1.w;
    }
    *(float4*)(rp + c0) = v0;
    *(float4*)(rp + c1) = v1;
    float s = v0.x + v0.y + v0.z + v0.w + v1.x + v1.y + v1.z + v1.w;
    float q = v0.x*v0.x + v0.y*v0.y + v0.z*v0.z + v0.w*v0.w +
              v1.x*v1.x + v1.y*v1.y + v1.z*v1.z + v1.w*v1.w;
#pragma unroll
    for (int o = 16; o > 0; o >>= 1) {
        s += __shfl_xor_sync(0xffffffffu, s, o);
        q += __shfl_xor_sync(0xffffffffu, q, o);
    }
    float m  = s * (1.f / 256.f);
    float var = q * (1.f / 256.f) - m * m;
    float rstd = rsqrtf(var + 1e-5f);
    float4 w0 = *(const float4*)(w + c0), w1 = *(const float4*)(w + c1);
    float4 b0 = *(const float4*)(bb + c0), b1 = *(const float4*)(bb + c1);
    float4 o0, o1;
    o0.x = (v0.x - m) * rstd * w0.x + b0.x;
    o0.y = (v0.y - m) * rstd * w0.y + b0.y;
    o0.z = (v0.z - m) * rstd * w0.z + b0.z;
    o0.w = (v0.w - m) * rstd * w0.w + b0.w;
    o1.x = (v1.x - m) * rstd * w1.x + b1.x;
    o1.y = (v1.y - m) * rstd * w1.y + b1.y;
    o1.z = (v1.z - m) * rstd * w1.z + b1.z;
    o1.w = (v1.w - m) * rstd * w1.w + b1.w;
    *(float4*)(op + c0) = o0;
    *(float4*)(op + c1) = o1;
}

// ---------------------------------------------------------------------------
// tc_nt (inproj): C[M,N] = A(M,K) * B(N,K)^T. Block 128x64, ktile 32,
// double-buffered smem pipeline. 8 warps 4(m)x2(n), warp 32x32.
// ---------------------------------------------------------------------------
#define NT_ASZ (128 * 36)
#define NT_BSZ (64 * 36)
#define NT_SMEM ((2 * NT_ASZ + 2 * NT_BSZ) * 4)

__global__ __launch_bounds__(256)
void tc_nt(const float* __restrict__ A, const float* __restrict__ B,
           float* __restrict__ C, int M, int N, int K) {
    extern __shared__ uint32_t sm_nt[];
    uint32_t* As = sm_nt;
    uint32_t* Bs = sm_nt + 2 * NT_ASZ;
    int tid = threadIdx.x, lane = tid & 31, wid = tid >> 5;
    int m0 = blockIdx.y * 128, n0 = blockIdx.x * 64;
    int wm = (wid >> 1) * 32, wn = (wid & 1) * 32;
    int gr = lane >> 2, gc = lane & 3;
    float acc[2][4][4];
#pragma unroll
    for (int i = 0; i < 2; i++)
#pragma unroll
        for (int j = 0; j < 4; j++)
#pragma unroll
            for (int q = 0; q < 4; q++) acc[i][j][q] = 0.f;
    int la_m = tid >> 3, la_k = (tid & 7) * 4;   // A: 4 rows (la_m+32i), 1 f4
    int lb_n = tid >> 2, lb_k = (tid & 3) * 8;   // B: 1 row, 2 f4
    const float* Apt = A + (size_t)(m0 + la_m) * K + la_k;
    const float* Bpt = B + (size_t)(n0 + lb_n) * K + lb_k;
    float4 ar[4], br[2];
#pragma unroll
    for (int i = 0; i < 4; i++) ar[i] = *(const float4*)(Apt + (size_t)(i * 32) * K);
    br[0] = *(const float4*)(Bpt);
    br[1] = *(const float4*)(Bpt + 4);
    int buf = 0;
#pragma unroll
    for (int i = 0; i < 4; i++)
        *(uint4*)&As[(la_m + i * 32) * 36 + la_k] = cvt4(ar[i]);
    *(uint4*)&Bs[lb_n * 36 + lb_k]     = cvt4(br[0]);
    *(uint4*)&Bs[lb_n * 36 + lb_k + 4] = cvt4(br[1]);
    __syncthreads();

    for (int k0 = 32; k0 <= K; k0 += 32) {
        if (k0 < K) {
#pragma unroll
            for (int i = 0; i < 4; i++)
                ar[i] = *(const float4*)(Apt + (size_t)(i * 32) * K + k0);
            br[0] = *(const float4*)(Bpt + k0);
            br[1] = *(const float4*)(Bpt + k0 + 4);
        }
        const uint32_t* Ab = As + buf * NT_ASZ;
        const uint32_t* Bb = Bs + buf * NT_BSZ;
#pragma unroll
        for (int ks = 0; ks < 4; ks++) {
            int kb = ks * 8;
            uint32_t a[2][4];
#pragma unroll
            for (int mi = 0; mi < 2; mi++) {
                int rb = wm + mi * 16 + gr;
                a[mi][0] = Ab[rb * 36 + kb + gc];
                a[mi][1] = Ab[(rb + 8) * 36 + kb + gc];
                a[mi][2] = Ab[rb * 36 + kb + gc + 4];
                a[mi][3] = Ab[(rb + 8) * 36 + kb + gc + 4];
            }
#pragma unroll
            for (int ni = 0; ni < 4; ni++) {
                uint32_t b0 = Bb[(wn + ni * 8 + gr) * 36 + kb + gc];
                uint32_t b1 = Bb[(wn + ni * 8 + gr) * 36 + kb + gc + 4];
#pragma unroll
                for (int mi = 0; mi < 2; mi++)
                    mma_tf32(acc[mi][ni], a[mi], b0, b1);
            }
        }
        if (k0 < K) {
            int nb = buf ^ 1;
#pragma unroll
            for (int i = 0; i < 4; i++)
                *(uint4*)&As[nb * NT_ASZ + (la_m + i * 32) * 36 + la_k] = cvt4(ar[i]);
            *(uint4*)&Bs[nb * NT_BSZ + lb_n * 36 + lb_k]     = cvt4(br[0]);
            *(uint4*)&Bs[nb * NT_BSZ + lb_n * 36 + lb_k + 4] = cvt4(br[1]);
            __syncthreads();
            buf = nb;
        }
    }
#pragma unroll
    for (int mi = 0; mi < 2; mi++) {
        int r0 = m0 + wm + mi * 16 + gr;
#pragma unroll
        for (int ni = 0; ni < 4; ni++) {
            int cc = n0 + wn + ni * 8 + 2 * gc;
            *(float2*)(C + (size_t)r0 * N + cc) =
                make_float2(acc[mi][ni][0], acc[mi][ni][1]);
            *(float2*)(C + (size_t)(r0 + 8) * N + cc) =
                make_float2(acc[mi][ni][2], acc[mi][ni][3]);
        }
    }
}

// ---------------------------------------------------------------------------
// tc_op (outproj): per batch, C'(dm=256, s) = W(256,512) x y(d,s); K=512.
// Double-buffered. Scatter epilogue into h (b,s,dm).
// ---------------------------------------------------------------------------
#define OP_ASZ (128 * 36)
#define OP_BSZ (32 * 72)
#define OP_SMEM ((2 * OP_ASZ + 2 * OP_BSZ) * 4)

__global__ __launch_bounds__(256)
void tc_op(const float* __restrict__ W, const float* __restrict__ Y,
           float* __restrict__ H) {
    extern __shared__ uint32_t sm_op[];
    uint32_t* As = sm_op;
    uint32_t* Bs = sm_op + 2 * OP_ASZ;
    int b = blockIdx.z;
    int m0 = blockIdx.y * 128, s0 = blockIdx.x * 64;
    const float* Yb = Y + (size_t)b * DI * NS;
    int tid = threadIdx.x, lane = tid & 31, wid = tid >> 5;
    int wm = (wid >> 1) * 32, wn = (wid & 1) * 32;
    int gr = lane >> 2, gc = lane & 3;
    float acc[2][4][4];
#pragma unroll
    for (int i = 0; i < 2; i++)
#pragma unroll
        for (int j = 0; j < 4; j++)
#pragma unroll
            for (int q = 0; q < 4; q++) acc[i][j][q] = 0.f;
    int la_m = tid >> 3, la_k = (tid & 7) * 4;
    int bk = tid >> 4, bn4 = (tid & 15) * 4;     // B: rows bk, bk+16; 1 f4 each
    const float* Apt = W + (size_t)(m0 + la_m) * DI + la_k;
    float4 ar[4], br[2];
#pragma unroll
    for (int i = 0; i < 4; i++) ar[i] = *(const float4*)(Apt + (size_t)(i * 32) * DI);
#pragma unroll
    for (int i = 0; i < 2; i++)
        br[i] = *(const float4*)(Yb + (size_t)(bk + i * 16) * NS + s0 + bn4);
    int buf = 0;
#pragma unroll
    for (int i = 0; i < 4; i++)
        *(uint4*)&As[(la_m + i * 32) * 36 + la_k] = cvt4(ar[i]);
#pragma unroll
    for (int i = 0; i < 2; i++)
        *(uint4*)&Bs[(bk + i * 16) * 72 + bn4] = cvt4(br[i]);
    __syncthreads();

    for (int k0 = 32; k0 <= DI; k0 += 32) {
        if (k0 < DI) {
#pragma unroll
            for (int i = 0; i < 4; i++)
                ar[i] = *(const float4*)(Apt + (size_t)(i * 32) * DI + k0);
#pragma unroll
            for (int i = 0; i < 2; i++)
                br[i] = *(const float4*)(Yb + (size_t)(k0 + bk + i * 16) * NS + s0 + bn4);
        }
        const uint32_t* Ab = As + buf * OP_ASZ;
        const uint32_t* Bb = Bs + buf * OP_BSZ;
#pragma unroll
        for (int ks = 0; ks < 4; ks++) {
            int kb = ks * 8;
            uint32_t a[2][4];
#pragma unroll
            for (int mi = 0; mi < 2; mi++) {
                int rb = wm + mi * 16 + gr;
                a[mi][0] = Ab[rb * 36 + kb + gc];
                a[mi][1] = Ab[(rb + 8) * 36 + kb + gc];
                a[mi][2] = Ab[rb * 36 + kb + gc + 4];
                a[mi][3] = Ab[(rb + 8) * 36 + kb + gc + 4];
            }
#pragma unroll
            for (int ni = 0; ni < 4; ni++) {
                int nn = wn + ni * 8 + gr;
                uint32_t b0 = Bb[(kb + gc) * 72 + nn];
                uint32_t b1 = Bb[(kb + gc + 4) * 72 + nn];
#pragma unroll
                for (int mi = 0; mi < 2; mi++)
                    mma_tf32(acc[mi][ni], a[mi], b0, b1);
            }
        }
        if (k0 < DI) {
            int nb = buf ^ 1;
#pragma unroll
            for (int i = 0; i < 4; i++)
                *(uint4*)&As[nb * OP_ASZ + (la_m + i * 32) * 36 + la_k] = cvt4(ar[i]);
#pragma unroll
            for (int i = 0; i < 2; i++)
                *(uint4*)&Bs[nb * OP_BSZ + (bk + i * 16) * 72 + bn4] = cvt4(br[i]);
            __syncthreads();
            buf = nb;
        }
    }
#pragma unroll
    for (int mi = 0; mi < 2; mi++) {
        int dm = m0 + wm + mi * 16 + gr;
#pragma unroll
        for (int ni = 0; ni < 4; ni++) {
            int s = s0 + wn + ni * 8 + 2 * gc;
            size_t r0 = (size_t)(b * NS + s) * DM;
            size_t r1 = (size_t)(b * NS + s + 1) * DM;
            H[r0 + dm]     = acc[mi][ni][0];
            H[r1 + dm]     = acc[mi][ni][1];
            H[r0 + dm + 8] = acc[mi][ni][2];
            H[r1 + dm + 8] = acc[mi][ni][3];
        }
    }
}

// ---------------------------------------------------------------------------
// tc_xp (xproj): per batch, dblt(48, s) = xpW(48,512) x xc(d,s); K=512.
// Block 64(m)x64(s), double-buffered. Warps 2(m)x4(n), warp 32x16.
// ---------------------------------------------------------------------------
#define XP_ASZ (64 * 36)
#define XP_BSZ (32 * 72)
#define XP_SMEM ((2 * XP_ASZ + 2 * XP_BSZ) * 4)

__global__ __launch_bounds__(256)
void tc_xp(const float* __restrict__ W, const float* __restrict__ X,
           float* __restrict__ Dt) {
    extern __shared__ uint32_t sm_xp[];
    uint32_t* As = sm_xp;
    uint32_t* Bs = sm_xp + 2 * XP_ASZ;
    int b = blockIdx.z;
    int s0 = blockIdx.x * 64;
    const float* Xb = X + (size_t)b * DI * NS;
    float* Db = Dt + (size_t)b * 48 * NS;
    int tid = threadIdx.x, lane = tid & 31, wid = tid >> 5;
    int wm = (wid >> 2) * 32, wn = (wid & 3) * 16;
    int gr = lane >> 2, gc = lane & 3;
    float acc[2][2][4];
#pragma unroll
    for (int i = 0; i < 2; i++)
#pragma unroll
        for (int j = 0; j < 2; j++)
#pragma unroll
            for (int q = 0; q < 4; q++) acc[i][j][q] = 0.f;
    int la_m = tid >> 2, la_k = (tid & 3) * 8;   // A: row la_m (0..63), 2 f4
    int bk = tid >> 4, bn4 = (tid & 15) * 4;
    bool avalid = (la_m < 48);
    const float* Apt = W + (size_t)la_m * DI + la_k;
    float4 ar[2], br[2];
    float4 zero = make_float4(0.f, 0.f, 0.f, 0.f);
    ar[0] = avalid ? *(const float4*)(Apt)     : zero;
    ar[1] = avalid ? *(const float4*)(Apt + 4) : zero;
#pragma unroll
    for (int i = 0; i < 2; i++)
        br[i] = *(const float4*)(Xb + (size_t)(bk + i * 16) * NS + s0 + bn4);
    int buf = 0;
    *(uint4*)&As[la_m * 36 + la_k]     = cvt4(ar[0]);
    *(uint4*)&As[la_m * 36 + la_k + 4] = cvt4(ar[1]);
#pragma unroll
    for (int i = 0; i < 2; i++)
        *(uint4*)&Bs[(bk + i * 16) * 72 + bn4] = cvt4(br[i]);
    __syncthreads();

    for (int k0 = 32; k0 <= DI; k0 += 32) {
        if (k0 < DI) {
            ar[0] = avalid ? *(const float4*)(Apt + k0)     : zero;
            ar[1] = avalid ? *(const float4*)(Apt + k0 + 4) : zero;
#pragma unroll
            for (int i = 0; i < 2; i++)
                br[i] = *(const float4*)(Xb + (size_t)(k0 + bk + i * 16) * NS + s0 + bn4);
        }
        const uint32_t* Ab = As + buf * XP_ASZ;
        const uint32_t* Bb = Bs + buf * XP_BSZ;
#pragma unroll
        for (int ks = 0; ks < 4; ks++) {
            int kb = ks * 8;
            uint32_t a[2][4];
#pragma unroll
            for (int mi = 0; mi < 2; mi++) {
                int rb = wm + mi * 16 + gr;
                a[mi][0] = Ab[rb * 36 + kb + gc];
                a[mi][1] = Ab[(rb + 8) * 36 + kb + gc];
                a[mi][2] = Ab[rb * 36 + kb + gc + 4];
                a[mi][3] = Ab[(rb + 8) * 36 + kb + gc + 4];
            }
#pragma unroll
            for (int ni = 0; ni < 2; ni++) {
                int nn = wn + ni * 8 + gr;
                uint32_t b0 = Bb[(kb + gc) * 72 + nn];
                uint32_t b1 = Bb[(kb + gc + 4) * 72 + nn];
#pragma unroll
                for (int mi = 0; mi < 2; mi++)
                    mma_tf32(acc[mi][ni], a[mi], b0, b1);
            }
        }
        if (k0 < DI) {
            int nb = buf ^ 1;
            *(uint4*)&As[nb * XP_ASZ + la_m * 36 + la_k]     = cvt4(ar[0]);
            *(uint4*)&As[nb * XP_ASZ + la_m * 36 + la_k + 4] = cvt4(ar[1]);
#pragma unroll
            for (int i = 0; i < 2; i++)
                *(uint4*)&Bs[nb * XP_BSZ + (bk + i * 16) * 72 + bn4] = cvt4(br[i]);
            __syncthreads();
            buf = nb;
        }
    }
#pragma unroll
    for (int mi = 0; mi < 2; mi++) {
        int m = wm + mi * 16 + gr;
#pragma unroll
        for (int ni = 0; ni < 2; ni++) {
            int sc = s0 + wn + ni * 8 + 2 * gc;
            if (m < 48)
                *(float2*)(Db + (size_t)m * NS + sc) =
                    make_float2(acc[mi][ni][0], acc[mi][ni][1]);
            if (m + 8 < 48)
                *(float2*)(Db + (size_t)(m + 8) * NS + sc) =
                    make_float2(acc[mi][ni][2], acc[mi][ni][3]);
        }
    }
}

// ---------------------------------------------------------------------------
// convz: fused causal depthwise conv (4 taps) + SiLU on x-half, and
// transpose+SiLU of z-half. xz (b,s,1024) -> xc (b,d,s), zt (b,d,s).
// Block: 32 d x 128 s. Conflict-free smem (pad 133), coalesced GMEM both ways.
// ---------------------------------------------------------------------------
__global__ __launch_bounds__(256)
void convz_kernel(const float* __restrict__ xz, const float* __restrict__ cw,
                  const float* __restrict__ cb, float* __restrict__ xc,
                  float* __restrict__ zt) {
    __shared__ float sx[32][133];   // [d][s], s index r = s0-3+r, r=0..130
    __shared__ float sz[32][133];   // [d][s], r=0..127
    __shared__ float swc[32][4];
    __shared__ float scb[32];
    int b = blockIdx.z, d0 = blockIdx.y * 32, s0 = blockIdx.x * 128;
    int tid = threadIdx.x;
    if (tid < 128) swc[tid >> 2][tid & 3] = cw[(d0 + (tid >> 2)) * 4 + (tid & 3)];
    if (tid < 32) scb[tid] = cb[d0 + tid];
    int c = tid & 31, r0 = tid >> 5;    // lanes over d (coalesced GMEM read)
    for (int r = r0; r < 131; r += 8) {
        int s = s0 - 3 + r;
        sx[c][r] = (s >= 0) ? xz[(size_t)(b * NS + s) * (2 * DI) + d0 + c] : 0.f;
    }
    for (int r = r0; r < 128; r += 8) {
        int s = s0 + r;
        sz[c][r] = xz[(size_t)(b * NS + s) * (2 * DI) + DI + d0 + c];
    }
    __syncthreads();
    int sl = tid & 127;                 // lanes over s (coalesced GMEM write)
    int dg = (tid >> 7) * 16;
#pragma unroll 4
    for (int dd = 0; dd < 16; dd++) {
        int d = dg + dd;
        float w0 = swc[d][0], w1 = swc[d][1], w2 = swc[d][2], w3 = swc[d][3];
        float bias = scb[d];
        float a = bias + w0 * sx[d][sl] + w1 * sx[d][sl + 1]
                       + w2 * sx[d][sl + 2] + w3 * sx[d][sl + 3];
        float o = a / (1.f + __expf(-a));
        xc[(size_t)(b * DI + d0 + d) * NS + s0 + sl] = o;
        float zv = sz[d][sl];
        zt[(size_t)(b * DI + d0 + d) * NS + s0 + sl] = zv / (1.f + __expf(-zv));
    }
}

// ---------------------------------------------------------------------------
// dtproj: dt(b,d,s) = softplus(dtW(512,16) @ dtpre(16,s) + dtb)
// ---------------------------------------------------------------------------
__device__ __forceinline__ float softplus_f(float x) {
    return (x > 20.f) ? x : log1pf(__expf(x));
}

__global__ __launch_bounds__(256)
void dtproj_kernel(const float* __restrict__ dblt, const float* __restrict__ W,
                   const float* __restrict__ bias, float* __restrict__ dt) {
    __shared__ float Ws[16][64];
    __shared__ float Ps[16][128];
    int b = blockIdx.z, d0 = blockIdx.y * 64, s0 = blockIdx.x * 128;
    int tid = threadIdx.x;
    {
        int dl = tid >> 2, k4 = (tid & 3) * 4;
        float4 wv = *(const float4*)(W + (size_t)(d0 + dl) * 16 + k4);
        Ws[k4 + 0][dl] = wv.x; Ws[k4 + 1][dl] = wv.y;
        Ws[k4 + 2][dl] = wv.z; Ws[k4 + 3][dl] = wv.w;
    }
    const float* P = dblt + (size_t)b * 48 * NS;
#pragma unroll
    for (int it = 0; it < 2; it++) {
        int lin = tid + it * 256;
        int r = lin >> 5, c4 = (lin & 31) * 4;
        *(float4*)&Ps[r][c4] = *(const float4*)(P + (size_t)r * NS + s0 + c4);
    }
    __syncthreads();
    int ty = tid >> 4, tx = tid & 15;
    float acc[4][8];
#pragma unroll
    for (int i = 0; i < 4; i++)
#pragma unroll
        for (int j = 0; j < 8; j++) acc[i][j] = 0.f;
#pragma unroll
    for (int r = 0; r < 16; r++) {
        float4 a4 = *(const float4*)&Ws[r][ty * 4];
        float4 p0 = *(const float4*)&Ps[r][tx * 8];
        float4 p1 = *(const float4*)&Ps[r][tx * 8 + 4];
        float am[4] = {a4.x, a4.y, a4.z, a4.w};
        float pn[8] = {p0.x, p0.y, p0.z, p0.w, p1.x, p1.y, p1.z, p1.w};
#pragma unroll
        for (int i = 0; i < 4; i++)
#pragma unroll
            for (int j = 0; j < 8; j++)
                acc[i][j] = fmaf(am[i], pn[j], acc[i][j]);
    }
#pragma unroll
    for (int i = 0; i < 4; i++) {
        int dv = d0 + ty * 4 + i;
        float bi = bias[dv];
        float o[8];
#pragma unroll
        for (int j = 0; j < 8; j++) o[j] = softplus_f(acc[i][j] + bi);
        float* op = dt + (size_t)(b * DI + dv) * NS + s0 + tx * 8;
        *(float4*)(op)     = make_float4(o[0], o[1], o[2], o[3]);
        *(float4*)(op + 4) = make_float4(o[4], o[5], o[6], o[7]);
    }
}

// ---------------------------------------------------------------------------
// scan
// ---------------------------------------------------------------------------
__global__ __launch_bounds__(128)
void scan_kernel(const float* __restrict__ dtp, const float* __restrict__ xcp,
                 const float* __restrict__ ztp, const float* __restrict__ dblt,
                 const float* __restrict__ Alog, const float* __restrict__ Dp,
                 float* __restrict__ yout) {
    int b = blockIdx.y;
    int warp = threadIdx.x >> 5, lane = threadIdx.x & 31;
    int dl = lane >> 4, n = lane & 15;
    int d = blockIdx.x * 8 + warp * 2 + dl;
    const float* dtr = dtp + (size_t)(b * DI + d) * NS;
    const float* xr  = xcp + (size_t)(b * DI + d) * NS;
    const float* zr  = ztp + (size_t)(b * DI + d) * NS;
    const float* Br  = dblt + (size_t)b * 48 * NS + (size_t)(16 + n) * NS;
    const float* Cr  = dblt + (size_t)b * 48 * NS + (size_t)(32 + n) * NS;
    float* yr = yout + (size_t)(b * DI + d) * NS;
    float a  = -__expf(Alog[d * DSTATE + n]);
    float Dv = Dp[d];
    float hst = 0.f;
    float4 dt4 = *(const float4*)dtr;
    float4 x4  = *(const float4*)xr;
    float4 z4  = *(const float4*)zr;
    float4 B4  = *(const float4*)Br;
    float4 C4  = *(const float4*)Cr;
    for (int t = 0; t < NS; t += 4) {
        float4 ndt = dt4, nx = x4, nz = z4, nB = B4, nC = C4;
        int t2 = t + 4;
        if (t2 < NS) {
            ndt = *(const float4*)(dtr + t2);
            nx  = *(const float4*)(xr + t2);
            nz  = *(const float4*)(zr + t2);
            nB  = *(const float4*)(Br + t2);
            nC  = *(const float4*)(Cr + t2);
        }
        float yo[4];
#pragma unroll
        for (int j = 0; j < 4; j++) {
            float dtv = (&dt4.x)[j], xv = (&x4.x)[j], zv = (&z4.x)[j];
            float Bv = (&B4.x)[j], Cv = (&C4.x)[j];
            float dA = __expf(dtv * a);
            hst = fmaf(dA, hst, dtv * xv * Bv);
            float p = hst * Cv;
            p += __shfl_xor_sync(0xffffffffu, p, 1);
            p += __shfl_xor_sync(0xffffffffu, p, 2);
            p += __shfl_xor_sync(0xffffffffu, p, 4);
            p += __shfl_xor_sync(0xffffffffu, p, 8);
            yo[j] = fmaf(Dv, xv, p) * zv;
        }
        if (n == 0)
            *(float4*)(yr + t) = make_float4(yo[0], yo[1], yo[2], yo[3]);
        dt4 = ndt; x4 = nx; z4 = nz; B4 = nB; C4 = nC;
    }
}

// ---------------------------------------------------------------------------
// head
// ---------------------------------------------------------------------------
__global__ __launch_bounds__(256)
void head_kernel(const float* __restrict__ hin, const float* __restrict__ w,
                 float* __restrict__ out) {
    int wid = threadIdx.x >> 5, lane = threadIdx.x & 31;
    int row = blockIdx.x * 8 + wid;
    const float* hp = hin + (size_t)row * DM;
    int c0 = lane * 4, c1 = 128 + lane * 4;
    float4 v0 = *(const float4*)(hp + c0);
    float4 v1 = *(const float4*)(hp + c1);
    float4 w0 = *(const float4*)(w + c0);
    float4 w1 = *(const float4*)(w + c1);
    float s = v0.x*w0.x + v0.y*w0.y + v0.z*w0.z + v0.w*w0.w +
              v1.x*w1.x + v1.y*w1.y + v1.z*w1.z + v1.w*w1.w;
#pragma unroll
    for (int o = 16; o > 0; o >>= 1) s += __shfl_xor_sync(0xffffffffu, s, o);
    if (lane == 0) out[row] = s;
}

// ---------------------------------------------------------------------------
// host
// ---------------------------------------------------------------------------
extern "C" void kernel_launch(void* const* d_in, const int* in_sizes, int n_in,
                              void* d_out, int out_size) {
    const float* x_src     = (const float*)d_in[0];
    const float* in_W      = (const float*)d_in[2];
    const float* norm_w    = (const float*)d_in[3];
    const float* norm_b    = (const float*)d_in[4];
    const float* inproj_W  = (const float*)d_in[5];
    const float* conv_w    = (const float*)d_in[6];
    const float* conv_b    = (const float*)d_in[7];
    const float* xproj_W   = (const float*)d_in[8];
    const float* dtproj_W  = (const float*)d_in[9];
    const float* dtproj_b  = (const float*)d_in[10];
    const float* A_log     = (const float*)d_in[11];
    const float* D_param   = (const float*)d_in[12];
    const float* outproj_W = (const float*)d_in[13];
    const float* out_W     = (const float*)d_in[14];
    float* out = (float*)d_out;

    static int smem_set = 0;
    if (!smem_set) {
        cudaFuncSetAttribute(tc_nt, cudaFuncAttributeMaxDynamicSharedMemorySize,
                             NT_SMEM);
        cudaFuncSetAttribute(tc_op, cudaFuncAttributeMaxDynamicSharedMemorySize,
                             OP_SMEM);
        cudaFuncSetAttribute(tc_xp, cudaFuncAttributeMaxDynamicSharedMemorySize,
                             XP_SMEM);
        smem_set = 1;
    }

    float *ph, *pres, *phn, *pxz, *pxc, *pzt, *pdblt, *pdt, *py;
    cudaGetSymbolAddress((void**)&ph,    g_h);
    cudaGetSymbolAddress((void**)&pres,  g_res);
    cudaGetSymbolAddress((void**)&phn,   g_hn);
    cudaGetSymbolAddress((void**)&pxz,   g_xz);
    cudaGetSymbolAddress((void**)&pxc,   g_xc);
    cudaGetSymbolAddress((void**)&pzt,   g_zt);
    cudaGetSymbolAddress((void**)&pdblt, g_dblt);
    cudaGetSymbolAddress((void**)&pdt,   g_dt);
    cudaGetSymbolAddress((void**)&py,    g_y);

    embed_kernel<<<NTOK, 256>>>(x_src, in_W, ph);

    for (int l = 0; l < 4; l++) {
        ln_kernel<<<NTOK / 8, 256>>>(ph, pres, phn,
                                     norm_w + l * DM, norm_b + l * DM,
                                     (l == 0) ? 1 : 0);
        tc_nt<<<dim3(1024 / 64, NTOK / 128), 256, NT_SMEM>>>(
            phn, inproj_W + (size_t)l * 1024 * DM, pxz, NTOK, 1024, DM);
        convz_kernel<<<dim3(NS / 128, DI / 32, NB), 256>>>(
            pxz, conv_w + (size_t)l * DI * 4, conv_b + (size_t)l * DI, pxc, pzt);
        tc_xp<<<dim3(NS / 64, 1, NB), 256, XP_SMEM>>>(
            xproj_W + (size_t)l * 48 * DI, pxc, pdblt);
        dtproj_kernel<<<dim3(NS / 128, DI / 64, NB), 256>>>(
            pdblt, dtproj_W + (size_t)l * DI * 16, dtproj_b + (size_t)l * DI, pdt);
        scan_kernel<<<dim3(DI / 8, NB), 128>>>(
            pdt, pxc, pzt, pdblt,
            A_log + (size_t)l * DI * DSTATE, D_param + (size_t)l * DI, py);
        tc_op<<<dim3(NS / 64, DM / 128, NB), 256, OP_SMEM>>>(
            outproj_W + (size_t)l * DM * DI, py, ph);
    }

    head_kernel<<<NTOK / 8, 256>>>(ph, out_W, out);
}

// round 7
// speedup vs baseline: 2.0398x; 1.4873x over previous
#include <cuda_runtime.h>
#include <cuda_bf16.h>
#include <cstdint>
#include <cstddef>

// ---------------------------------------------------------------------------
// Mamba model. GEMMs: double-buffered tf32 mma.sync. Scan: fused dtproj +
// smem-staged chunks. inproj epilogue writes transposed xt/zt directly.
// Layouts: h/res/hn (b,s,f) row-major; xt/zt/xc/y (b,d,s); dblt (b,j,s).
// ---------------------------------------------------------------------------

#define NB     4
#define NS     2048
#define DM     256
#define DI     512
#define DSTATE 16
#define NTOK   (NB * NS)

__device__ float g_h   [NTOK * DM];
__device__ float g_res [NTOK * DM];
__device__ float g_hn  [NTOK * DM];
__device__ float g_xt  [NB * DI * NS];   // raw conv input, (b,d,s)
__device__ float g_zt  [NB * DI * NS];   // silu(z), (b,d,s)
__device__ float g_xc  [NB * DI * NS];   // conv+silu output, (b,d,s)
__device__ float g_dblt[NB * 48 * NS];
__device__ float g_y   [NB * DI * NS];

// ---------------------------------------------------------------------------
__device__ __forceinline__ uint32_t f2tf(float x) {
    uint32_t u;
    asm("cvt.rna.tf32.f32 %0, %1;" : "=r"(u) : "f"(x));
    return u;
}

__device__ __forceinline__ void mma_tf32(float* c, const uint32_t* a,
                                         uint32_t b0, uint32_t b1) {
    asm volatile(
        "mma.sync.aligned.m16n8k8.row.col.f32.tf32.tf32.f32 "
        "{%0,%1,%2,%3},{%4,%5,%6,%7},{%8,%9},{%0,%1,%2,%3};"
        : "+f"(c[0]), "+f"(c[1]), "+f"(c[2]), "+f"(c[3])
        : "r"(a[0]), "r"(a[1]), "r"(a[2]), "r"(a[3]), "r"(b0), "r"(b1));
}

__device__ __forceinline__ uint4 cvt4(float4 v) {
    uint4 u;
    u.x = f2tf(v.x); u.y = f2tf(v.y); u.z = f2tf(v.z); u.w = f2tf(v.w);
    return u;
}

__device__ __forceinline__ float silu_f(float x) {
    return x / (1.f + __expf(-x));
}

__device__ __forceinline__ float softplus_f(float x) {
    return (x > 20.f) ? x : log1pf(__expf(x));
}

// ---------------------------------------------------------------------------
// embed
// ---------------------------------------------------------------------------
__global__ __launch_bounds__(256)
void embed_kernel(const float* __restrict__ x, const float* __restrict__ W,
                  float* __restrict__ h) {
    __shared__ float xs[15];
    int row = blockIdx.x;
    if (threadIdx.x < 15) xs[threadIdx.x] = x[row * 15 + threadIdx.x];
    __syncthreads();
    int m = threadIdx.x;
    const float* wr = W + m * 15;
    float acc = 0.f;
#pragma unroll
    for (int k = 0; k < 15; k++) acc = fmaf(xs[k], wr[k], acc);
    h[(size_t)row * DM + m] = acc;
}

// ---------------------------------------------------------------------------
// fused residual + layernorm
// ---------------------------------------------------------------------------
__global__ __launch_bounds__(256)
void ln_kernel(const float* __restrict__ hin, float* __restrict__ res,
               float* __restrict__ hn, const float* __restrict__ w,
               const float* __restrict__ bb, int first) {
    int wid = threadIdx.x >> 5, lane = threadIdx.x & 31;
    int row = blockIdx.x * 8 + wid;
    const float* hp = hin + (size_t)row * DM;
    float* rp = res + (size_t)row * DM;
    float* op = hn + (size_t)row * DM;
    int c0 = lane * 4, c1 = 128 + lane * 4;
    float4 v0 = *(const float4*)(hp + c0);
    float4 v1 = *(const float4*)(hp + c1);
    if (!first) {
        float4 r0 = *(const float4*)(rp + c0);
        float4 r1 = *(const float4*)(rp + c1);
        v0.x += r0.x; v0.y += r0.y; v0.z += r0.z; v0.w += r0.w;
        v1.x += r1.x; v1.y += r1.y; v1.z += r1.z; v1.w += r1.w;
    }
    *(float4*)(rp + c0) = v0;
    *(float4*)(rp + c1) = v1;
    float s = v0.x + v0.y + v0.z + v0.w + v1.x + v1.y + v1.z + v1.w;
    float q = v0.x*v0.x + v0.y*v0.y + v0.z*v0.z + v0.w*v0.w +
              v1.x*v1.x + v1.y*v1.y + v1.z*v1.z + v1.w*v1.w;
#pragma unroll
    for (int o = 16; o > 0; o >>= 1) {
        s += __shfl_xor_sync(0xffffffffu, s, o);
        q += __shfl_xor_sync(0xffffffffu, q, o);
    }
    float m  = s * (1.f / 256.f);
    float var = q * (1.f / 256.f) - m * m;
    float rstd = rsqrtf(var + 1e-5f);
    float4 w0 = *(const float4*)(w + c0), w1 = *(const float4*)(w + c1);
    float4 b0 = *(const float4*)(bb + c0), b1 = *(const float4*)(bb + c1);
    float4 o0, o1;
    o0.x = (v0.x - m) * rstd * w0.x + b0.x;
    o0.y = (v0.y - m) * rstd * w0.y + b0.y;
    o0.z = (v0.z - m) * rstd * w0.z + b0.z;
    o0.w = (v0.w - m) * rstd * w0.w + b0.w;
    o1.x = (v1.x - m) * rstd * w1.x + b1.x;
    o1.y = (v1.y - m) * rstd * w1.y + b1.y;
    o1.z = (v1.z - m) * rstd * w1.z + b1.z;
    o1.w = (v1.w - m) * rstd * w1.w + b1.w;
    *(float4*)(op + c0) = o0;
    *(float4*)(op + c1) = o1;
}

// ---------------------------------------------------------------------------
// tc_in (inproj): xz = hn(8192,256) * W(1024,256)^T, but epilogue writes
// TRANSPOSED: features <512 -> xt (b,d,s) raw; >=512 -> zt (b,d,s) silu'd.
// Block 128(tok)x64(feat), ktile 32, double-buffered.
// ---------------------------------------------------------------------------
#define NT_ASZ (128 * 36)
#define NT_BSZ (64 * 36)
#define NT_SMEM ((2 * NT_ASZ + 2 * NT_BSZ) * 4)

__global__ __launch_bounds__(256)
void tc_in(const float* __restrict__ A, const float* __restrict__ B,
           float* __restrict__ xt, float* __restrict__ zt) {
    const int K = DM, N = 1024;
    extern __shared__ uint32_t sm_nt[];
    uint32_t* As = sm_nt;
    uint32_t* Bs = sm_nt + 2 * NT_ASZ;
    int tid = threadIdx.x, lane = tid & 31, wid = tid >> 5;
    int m0 = blockIdx.y * 128, n0 = blockIdx.x * 64;
    int wm = (wid >> 1) * 32, wn = (wid & 1) * 32;
    int gr = lane >> 2, gc = lane & 3;
    float acc[2][4][4];
#pragma unroll
    for (int i = 0; i < 2; i++)
#pragma unroll
        for (int j = 0; j < 4; j++)
#pragma unroll
            for (int q = 0; q < 4; q++) acc[i][j][q] = 0.f;
    int la_m = tid >> 3, la_k = (tid & 7) * 4;
    int lb_n = tid >> 2, lb_k = (tid & 3) * 8;
    const float* Apt = A + (size_t)(m0 + la_m) * K + la_k;
    const float* Bpt = B + (size_t)(n0 + lb_n) * K + lb_k;
    float4 ar[4], br[2];
#pragma unroll
    for (int i = 0; i < 4; i++) ar[i] = *(const float4*)(Apt + (size_t)(i * 32) * K);
    br[0] = *(const float4*)(Bpt);
    br[1] = *(const float4*)(Bpt + 4);
    int buf = 0;
#pragma unroll
    for (int i = 0; i < 4; i++)
        *(uint4*)&As[(la_m + i * 32) * 36 + la_k] = cvt4(ar[i]);
    *(uint4*)&Bs[lb_n * 36 + lb_k]     = cvt4(br[0]);
    *(uint4*)&Bs[lb_n * 36 + lb_k + 4] = cvt4(br[1]);
    __syncthreads();

    for (int k0 = 32; k0 <= K; k0 += 32) {
        if (k0 < K) {
#pragma unroll
            for (int i = 0; i < 4; i++)
                ar[i] = *(const float4*)(Apt + (size_t)(i * 32) * K + k0);
            br[0] = *(const float4*)(Bpt + k0);
            br[1] = *(const float4*)(Bpt + k0 + 4);
        }
        const uint32_t* Ab = As + buf * NT_ASZ;
        const uint32_t* Bb = Bs + buf * NT_BSZ;
#pragma unroll
        for (int ks = 0; ks < 4; ks++) {
            int kb = ks * 8;
            uint32_t a[2][4];
#pragma unroll
            for (int mi = 0; mi < 2; mi++) {
                int rb = wm + mi * 16 + gr;
                a[mi][0] = Ab[rb * 36 + kb + gc];
                a[mi][1] = Ab[(rb + 8) * 36 + kb + gc];
                a[mi][2] = Ab[rb * 36 + kb + gc + 4];
                a[mi][3] = Ab[(rb + 8) * 36 + kb + gc + 4];
            }
#pragma unroll
            for (int ni = 0; ni < 4; ni++) {
                uint32_t b0 = Bb[(wn + ni * 8 + gr) * 36 + kb + gc];
                uint32_t b1 = Bb[(wn + ni * 8 + gr) * 36 + kb + gc + 4];
#pragma unroll
                for (int mi = 0; mi < 2; mi++)
                    mma_tf32(acc[mi][ni], a[mi], b0, b1);
            }
        }
        if (k0 < K) {
            int nb = buf ^ 1;
#pragma unroll
            for (int i = 0; i < 4; i++)
                *(uint4*)&As[nb * NT_ASZ + (la_m + i * 32) * 36 + la_k] = cvt4(ar[i]);
            *(uint4*)&Bs[nb * NT_BSZ + lb_n * 36 + lb_k]     = cvt4(br[0]);
            *(uint4*)&Bs[nb * NT_BSZ + lb_n * 36 + lb_k + 4] = cvt4(br[1]);
            __syncthreads();
            buf = nb;
        }
    }
    // ---- transpose epilogue via smem: st[feat 0..63][tok 0..127], stride 132
    float* st = (float*)sm_nt;
    __syncthreads();
#pragma unroll
    for (int mi = 0; mi < 2; mi++) {
        int r0 = wm + mi * 16 + gr;
#pragma unroll
        for (int ni = 0; ni < 4; ni++) {
            int cc = wn + ni * 8 + 2 * gc;
            st[cc * 132 + r0]           = acc[mi][ni][0];
            st[(cc + 1) * 132 + r0]     = acc[mi][ni][1];
            st[cc * 132 + r0 + 8]       = acc[mi][ni][2];
            st[(cc + 1) * 132 + r0 + 8] = acc[mi][ni][3];
        }
    }
    __syncthreads();
    int b = m0 / NS, s0 = m0 % NS;
#pragma unroll
    for (int rr = wid; rr < 64; rr += 8) {
        int f = n0 + rr;
        float4 v = *(float4*)&st[rr * 132 + lane * 4];
        if (f < DI) {
            *(float4*)(xt + ((size_t)b * DI + f) * NS + s0 + lane * 4) = v;
        } else {
            v.x = silu_f(v.x); v.y = silu_f(v.y);
            v.z = silu_f(v.z); v.w = silu_f(v.w);
            *(float4*)(zt + ((size_t)b * DI + f - DI) * NS + s0 + lane * 4) = v;
        }
    }
}

// ---------------------------------------------------------------------------
// conv_t: causal 4-tap depthwise conv + SiLU on (b,d,s) layout. One block per
// (d,b); 256 threads x 8 s each = 2048 s. Fully coalesced streaming.
// ---------------------------------------------------------------------------
__global__ __launch_bounds__(256)
void conv_t(const float* __restrict__ xt, const float* __restrict__ cw,
            const float* __restrict__ cb, float* __restrict__ xc) {
    int d = blockIdx.x, b = blockIdx.y;
    const float* row = xt + ((size_t)b * DI + d) * NS;
    float* orow = xc + ((size_t)b * DI + d) * NS;
    float w0 = cw[d * 4 + 0], w1 = cw[d * 4 + 1];
    float w2 = cw[d * 4 + 2], w3 = cw[d * 4 + 3];
    float bias = cb[d];
    int s = threadIdx.x * 8;
    float in[12];
    float4 A = (s == 0) ? make_float4(0.f, 0.f, 0.f, 0.f)
                        : *(const float4*)(row + s - 4);
    float4 Bv = *(const float4*)(row + s);
    float4 Cv = *(const float4*)(row + s + 4);
    in[0] = A.x; in[1] = A.y; in[2] = A.z; in[3] = A.w;
    in[4] = Bv.x; in[5] = Bv.y; in[6] = Bv.z; in[7] = Bv.w;
    in[8] = Cv.x; in[9] = Cv.y; in[10] = Cv.z; in[11] = Cv.w;
    float o[8];
#pragma unroll
    for (int k = 0; k < 8; k++) {
        float a = bias + w0 * in[k + 1] + w1 * in[k + 2]
                       + w2 * in[k + 3] + w3 * in[k + 4];
        o[k] = silu_f(a);
    }
    *(float4*)(orow + s)     = make_float4(o[0], o[1], o[2], o[3]);
    *(float4*)(orow + s + 4) = make_float4(o[4], o[5], o[6], o[7]);
}

// ---------------------------------------------------------------------------
// tc_xp (xproj): per batch, dblt(48, s) = xpW(48,512) x xc(d,s); K=512.
// ---------------------------------------------------------------------------
#define XP_ASZ (64 * 36)
#define XP_BSZ (32 * 72)
#define XP_SMEM ((2 * XP_ASZ + 2 * XP_BSZ) * 4)

__global__ __launch_bounds__(256)
void tc_xp(const float* __restrict__ W, const float* __restrict__ X,
           float* __restrict__ Dt) {
    extern __shared__ uint32_t sm_xp[];
    uint32_t* As = sm_xp;
    uint32_t* Bs = sm_xp + 2 * XP_ASZ;
    int b = blockIdx.z;
    int s0 = blockIdx.x * 64;
    const float* Xb = X + (size_t)b * DI * NS;
    float* Db = Dt + (size_t)b * 48 * NS;
    int tid = threadIdx.x, lane = tid & 31, wid = tid >> 5;
    int wm = (wid >> 2) * 32, wn = (wid & 3) * 16;
    int gr = lane >> 2, gc = lane & 3;
    float acc[2][2][4];
#pragma unroll
    for (int i = 0; i < 2; i++)
#pragma unroll
        for (int j = 0; j < 2; j++)
#pragma unroll
            for (int q = 0; q < 4; q++) acc[i][j][q] = 0.f;
    int la_m = tid >> 2, la_k = (tid & 3) * 8;
    int bk = tid >> 4, bn4 = (tid & 15) * 4;
    bool avalid = (la_m < 48);
    const float* Apt = W + (size_t)la_m * DI + la_k;
    float4 ar[2], br[2];
    float4 zero = make_float4(0.f, 0.f, 0.f, 0.f);
    ar[0] = avalid ? *(const float4*)(Apt)     : zero;
    ar[1] = avalid ? *(const float4*)(Apt + 4) : zero;
#pragma unroll
    for (int i = 0; i < 2; i++)
        br[i] = *(const float4*)(Xb + (size_t)(bk + i * 16) * NS + s0 + bn4);
    int buf = 0;
    *(uint4*)&As[la_m * 36 + la_k]     = cvt4(ar[0]);
    *(uint4*)&As[la_m * 36 + la_k + 4] = cvt4(ar[1]);
#pragma unroll
    for (int i = 0; i < 2; i++)
        *(uint4*)&Bs[(bk + i * 16) * 72 + bn4] = cvt4(br[i]);
    __syncthreads();

    for (int k0 = 32; k0 <= DI; k0 += 32) {
        if (k0 < DI) {
            ar[0] = avalid ? *(const float4*)(Apt + k0)     : zero;
            ar[1] = avalid ? *(const float4*)(Apt + k0 + 4) : zero;
#pragma unroll
            for (int i = 0; i < 2; i++)
                br[i] = *(const float4*)(Xb + (size_t)(k0 + bk + i * 16) * NS + s0 + bn4);
        }
        const uint32_t* Ab = As + buf * XP_ASZ;
        const uint32_t* Bb = Bs + buf * XP_BSZ;
#pragma unroll
        for (int ks = 0; ks < 4; ks++) {
            int kb = ks * 8;
            uint32_t a[2][4];
#pragma unroll
            for (int mi = 0; mi < 2; mi++) {
                int rb = wm + mi * 16 + gr;
                a[mi][0] = Ab[rb * 36 + kb + gc];
                a[mi][1] = Ab[(rb + 8) * 36 + kb + gc];
                a[mi][2] = Ab[rb * 36 + kb + gc + 4];
                a[mi][3] = Ab[(rb + 8) * 36 + kb + gc + 4];
            }
#pragma unroll
            for (int ni = 0; ni < 2; ni++) {
                int nn = wn + ni * 8 + gr;
                uint32_t b0 = Bb[(kb + gc) * 72 + nn];
                uint32_t b1 = Bb[(kb + gc + 4) * 72 + nn];
#pragma unroll
                for (int mi = 0; mi < 2; mi++)
                    mma_tf32(acc[mi][ni], a[mi], b0, b1);
            }
        }
        if (k0 < DI) {
            int nb = buf ^ 1;
            *(uint4*)&As[nb * XP_ASZ + la_m * 36 + la_k]     = cvt4(ar[0]);
            *(uint4*)&As[nb * XP_ASZ + la_m * 36 + la_k + 4] = cvt4(ar[1]);
#pragma unroll
            for (int i = 0; i < 2; i++)
                *(uint4*)&Bs[nb * XP_BSZ + (bk + i * 16) * 72 + bn4] = cvt4(br[i]);
            __syncthreads();
            buf = nb;
        }
    }
#pragma unroll
    for (int mi = 0; mi < 2; mi++) {
        int m = wm + mi * 16 + gr;
#pragma unroll
        for (int ni = 0; ni < 2; ni++) {
            int sc = s0 + wn + ni * 8 + 2 * gc;
            if (m < 48)
                *(float2*)(Db + (size_t)m * NS + sc) =
                    make_float2(acc[mi][ni][0], acc[mi][ni][1]);
            if (m + 8 < 48)
                *(float2*)(Db + (size_t)(m + 8) * NS + sc) =
                    make_float2(acc[mi][ni][2], acc[mi][ni][3]);
        }
    }
}

// ---------------------------------------------------------------------------
// scan v2: fused dtproj + chunked smem staging.
// Block = 128 threads (4 warps) = 8 channels d. Lane = (dl<<4)|n.
// Per 64-step chunk: cooperatively stage dtpre/B/C/x/z, compute
// dt=softplus(W@dtpre+b) in smem, run the recurrence, write y chunk coalesced.
// ---------------------------------------------------------------------------
#define SCH 64

__global__ __launch_bounds__(128)
void scan_kernel(const float* __restrict__ xcp, const float* __restrict__ ztp,
                 const float* __restrict__ dblt,
                 const float* __restrict__ dtW, const float* __restrict__ dtb,
                 const float* __restrict__ Alog, const float* __restrict__ Dp,
                 float* __restrict__ yout) {
    __shared__ float sdp[16][SCH];       // dtpre chunk (j, t)
    __shared__ float sB [16][SCH + 4];   // stride 68
    __shared__ float sC [16][SCH + 4];
    __shared__ float sdt[8][SCH + 4];
    __shared__ float sx [8][SCH + 4];
    __shared__ float sz [8][SCH + 4];
    __shared__ float sy [8][SCH + 4];
    __shared__ float sW [8][16];
    __shared__ float sbias[8];

    int b = blockIdx.y;
    int d0 = blockIdx.x * 8;
    int tid = threadIdx.x, lane = tid & 31, warp = tid >> 5;
    int dl = lane >> 4, n = lane & 15;
    int dloc = warp * 2 + dl;
    int d = d0 + dloc;

    {
        int dd = tid >> 4, j = tid & 15;
        sW[dd][j] = dtW[(size_t)(d0 + dd) * 16 + j];
    }
    if (tid < 8) sbias[tid] = dtb[d0 + tid];

    float a  = -__expf(Alog[d * DSTATE + n]);
    float Dv = Dp[d];
    float hst = 0.f;
    const float* dpb = dblt + (size_t)b * 48 * NS;

    for (int t0 = 0; t0 < NS; t0 += SCH) {
        // stage chunk
        {
            int r = tid >> 3, c = (tid & 7) * 8;
            *(float4*)&sdp[r][c]     = *(const float4*)(dpb + (size_t)r * NS + t0 + c);
            *(float4*)&sdp[r][c + 4] = *(const float4*)(dpb + (size_t)r * NS + t0 + c + 4);
            *(float4*)&sB[r][c]      = *(const float4*)(dpb + (size_t)(16 + r) * NS + t0 + c);
            *(float4*)&sB[r][c + 4]  = *(const float4*)(dpb + (size_t)(16 + r) * NS + t0 + c + 4);
            *(float4*)&sC[r][c]      = *(const float4*)(dpb + (size_t)(32 + r) * NS + t0 + c);
            *(float4*)&sC[r][c + 4]  = *(const float4*)(dpb + (size_t)(32 + r) * NS + t0 + c + 4);
        }
        {
            int r = tid >> 4, c = (tid & 15) * 4;
            *(float4*)&sx[r][c] = *(const float4*)(xcp + ((size_t)b * DI + d0 + r) * NS + t0 + c);
            *(float4*)&sz[r][c] = *(const float4*)(ztp + ((size_t)b * DI + d0 + r) * NS + t0 + c);
        }
        __syncthreads();
        // dt = softplus(W @ dtpre + b): thread computes 4 t's for one d
        {
            int dd = tid >> 4, tt = (tid & 15) * 4;
            float bi = sbias[dd];
            float a0 = bi, a1 = bi, a2 = bi, a3 = bi;
#pragma unroll
            for (int j = 0; j < 16; j++) {
                float w = sW[dd][j];
                a0 = fmaf(w, sdp[j][tt],     a0);
                a1 = fmaf(w, sdp[j][tt + 1], a1);
                a2 = fmaf(w, sdp[j][tt + 2], a2);
                a3 = fmaf(w, sdp[j][tt + 3], a3);
            }
            sdt[dd][tt]     = softplus_f(a0);
            sdt[dd][tt + 1] = softplus_f(a1);
            sdt[dd][tt + 2] = softplus_f(a2);
            sdt[dd][tt + 3] = softplus_f(a3);
        }
        __syncthreads();
        // recurrence over chunk
        for (int g = 0; g < SCH; g += 4) {
            float4 dt4 = *(const float4*)&sdt[dloc][g];
            float4 x4  = *(const float4*)&sx[dloc][g];
            float4 z4  = *(const float4*)&sz[dloc][g];
            float4 B4  = *(const float4*)&sB[n][g];
            float4 C4  = *(const float4*)&sC[n][g];
            float yo[4];
#pragma unroll
            for (int j = 0; j < 4; j++) {
                float dtv = (&dt4.x)[j], xv = (&x4.x)[j], zv = (&z4.x)[j];
                float Bv = (&B4.x)[j], Cv = (&C4.x)[j];
                float dA = __expf(dtv * a);
                hst = fmaf(dA, hst, dtv * xv * Bv);
                float p = hst * Cv;
                p += __shfl_xor_sync(0xffffffffu, p, 1);
                p += __shfl_xor_sync(0xffffffffu, p, 2);
                p += __shfl_xor_sync(0xffffffffu, p, 4);
                p += __shfl_xor_sync(0xffffffffu, p, 8);
                yo[j] = fmaf(Dv, xv, p) * zv;
            }
            if (n == 0)
                *(float4*)&sy[dloc][g] = make_float4(yo[0], yo[1], yo[2], yo[3]);
        }
        __syncthreads();
        // write y chunk coalesced
        {
            int r = tid >> 4, c = (tid & 15) * 4;
            *(float4*)(yout + ((size_t)b * DI + d0 + r) * NS + t0 + c) =
                *(float4*)&sy[r][c];
        }
    }
}

// ---------------------------------------------------------------------------
// tc_op (outproj): per batch, C'(dm, s) = W(256,512) x y(d,s); K=512.
// Scatter epilogue into h (b,s,dm).
// ---------------------------------------------------------------------------
#define OP_ASZ (128 * 36)
#define OP_BSZ (32 * 72)
#define OP_SMEM ((2 * OP_ASZ + 2 * OP_BSZ) * 4)

__global__ __launch_bounds__(256)
void tc_op(const float* __restrict__ W, const float* __restrict__ Y,
           float* __restrict__ H) {
    extern __shared__ uint32_t sm_op[];
    uint32_t* As = sm_op;
    uint32_t* Bs = sm_op + 2 * OP_ASZ;
    int b = blockIdx.z;
    int m0 = blockIdx.y * 128, s0 = blockIdx.x * 64;
    const float* Yb = Y + (size_t)b * DI * NS;
    int tid = threadIdx.x, lane = tid & 31, wid = tid >> 5;
    int wm = (wid >> 1) * 32, wn = (wid & 1) * 32;
    int gr = lane >> 2, gc = lane & 3;
    float acc[2][4][4];
#pragma unroll
    for (int i = 0; i < 2; i++)
#pragma unroll
        for (int j = 0; j < 4; j++)
#pragma unroll
            for (int q = 0; q < 4; q++) acc[i][j][q] = 0.f;
    int la_m = tid >> 3, la_k = (tid & 7) * 4;
    int bk = tid >> 4, bn4 = (tid & 15) * 4;
    const float* Apt = W + (size_t)(m0 + la_m) * DI + la_k;
    float4 ar[4], br[2];
#pragma unroll
    for (int i = 0; i < 4; i++) ar[i] = *(const float4*)(Apt + (size_t)(i * 32) * DI);
#pragma unroll
    for (int i = 0; i < 2; i++)
        br[i] = *(const float4*)(Yb + (size_t)(bk + i * 16) * NS + s0 + bn4);
    int buf = 0;
#pragma unroll
    for (int i = 0; i < 4; i++)
        *(uint4*)&As[(la_m + i * 32) * 36 + la_k] = cvt4(ar[i]);
#pragma unroll
    for (int i = 0; i < 2; i++)
        *(uint4*)&Bs[(bk + i * 16) * 72 + bn4] = cvt4(br[i]);
    __syncthreads();

    for (int k0 = 32; k0 <= DI; k0 += 32) {
        if (k0 < DI) {
#pragma unroll
            for (int i = 0; i < 4; i++)
                ar[i] = *(const float4*)(Apt + (size_t)(i * 32) * DI + k0);
#pragma unroll
            for (int i = 0; i < 2; i++)
                br[i] = *(const float4*)(Yb + (size_t)(k0 + bk + i * 16) * NS + s0 + bn4);
        }
        const uint32_t* Ab = As + buf * OP_ASZ;
        const uint32_t* Bb = Bs + buf * OP_BSZ;
#pragma unroll
        for (int ks = 0; ks < 4; ks++) {
            int kb = ks * 8;
            uint32_t a[2][4];
#pragma unroll
            for (int mi = 0; mi < 2; mi++) {
                int rb = wm + mi * 16 + gr;
                a[mi][0] = Ab[rb * 36 + kb + gc];
                a[mi][1] = Ab[(rb + 8) * 36 + kb + gc];
                a[mi][2] = Ab[rb * 36 + kb + gc + 4];
                a[mi][3] = Ab[(rb + 8) * 36 + kb + gc + 4];
            }
#pragma unroll
            for (int ni = 0; ni < 4; ni++) {
                int nn = wn + ni * 8 + gr;
                uint32_t b0 = Bb[(kb + gc) * 72 + nn];
                uint32_t b1 = Bb[(kb + gc + 4) * 72 + nn];
#pragma unroll
                for (int mi = 0; mi < 2; mi++)
                    mma_tf32(acc[mi][ni], a[mi], b0, b1);
            }
        }
        if (k0 < DI) {
            int nb = buf ^ 1;
#pragma unroll
            for (int i = 0; i < 4; i++)
                *(uint4*)&As[nb * OP_ASZ + (la_m + i * 32) * 36 + la_k] = cvt4(ar[i]);
#pragma unroll
            for (int i = 0; i < 2; i++)
                *(uint4*)&Bs[nb * OP_BSZ + (bk + i * 16) * 72 + bn4] = cvt4(br[i]);
            __syncthreads();
            buf = nb;
        }
    }
#pragma unroll
    for (int mi = 0; mi < 2; mi++) {
        int dm = m0 + wm + mi * 16 + gr;
#pragma unroll
        for (int ni = 0; ni < 4; ni++) {
            int s = s0 + wn + ni * 8 + 2 * gc;
            size_t r0 = (size_t)(b * NS + s) * DM;
            size_t r1 = (size_t)(b * NS + s + 1) * DM;
            H[r0 + dm]     = acc[mi][ni][0];
            H[r1 + dm]     = acc[mi][ni][1];
            H[r0 + dm + 8] = acc[mi][ni][2];
            H[r1 + dm + 8] = acc[mi][ni][3];
        }
    }
}

// ---------------------------------------------------------------------------
// head
// ---------------------------------------------------------------------------
__global__ __launch_bounds__(256)
void head_kernel(const float* __restrict__ hin, const float* __restrict__ w,
                 float* __restrict__ out) {
    int wid = threadIdx.x >> 5, lane = threadIdx.x & 31;
    int row = blockIdx.x * 8 + wid;
    const float* hp = hin + (size_t)row * DM;
    int c0 = lane * 4, c1 = 128 + lane * 4;
    float4 v0 = *(const float4*)(hp + c0);
    float4 v1 = *(const float4*)(hp + c1);
    float4 w0 = *(const float4*)(w + c0);
    float4 w1 = *(const float4*)(w + c1);
    float s = v0.x*w0.x + v0.y*w0.y + v0.z*w0.z + v0.w*w0.w +
              v1.x*w1.x + v1.y*w1.y + v1.z*w1.z + v1.w*w1.w;
#pragma unroll
    for (int o = 16; o > 0; o >>= 1) s += __shfl_xor_sync(0xffffffffu, s, o);
    if (lane == 0) out[row] = s;
}

// ---------------------------------------------------------------------------
// host
// ---------------------------------------------------------------------------
extern "C" void kernel_launch(void* const* d_in, const int* in_sizes, int n_in,
                              void* d_out, int out_size) {
    const float* x_src     = (const float*)d_in[0];
    const float* in_W      = (const float*)d_in[2];
    const float* norm_w    = (const float*)d_in[3];
    const float* norm_b    = (const float*)d_in[4];
    const float* inproj_W  = (const float*)d_in[5];
    const float* conv_w    = (const float*)d_in[6];
    const float* conv_b    = (const float*)d_in[7];
    const float* xproj_W   = (const float*)d_in[8];
    const float* dtproj_W  = (const float*)d_in[9];
    const float* dtproj_b  = (const float*)d_in[10];
    const float* A_log     = (const float*)d_in[11];
    const float* D_param   = (const float*)d_in[12];
    const float* outproj_W = (const float*)d_in[13];
    const float* out_W     = (const float*)d_in[14];
    float* out = (float*)d_out;

    static int smem_set = 0;
    if (!smem_set) {
        cudaFuncSetAttribute(tc_in, cudaFuncAttributeMaxDynamicSharedMemorySize,
                             NT_SMEM);
        cudaFuncSetAttribute(tc_op, cudaFuncAttributeMaxDynamicSharedMemorySize,
                             OP_SMEM);
        cudaFuncSetAttribute(tc_xp, cudaFuncAttributeMaxDynamicSharedMemorySize,
                             XP_SMEM);
        smem_set = 1;
    }

    float *ph, *pres, *phn, *pxt, *pzt, *pxc, *pdblt, *py;
    cudaGetSymbolAddress((void**)&ph,    g_h);
    cudaGetSymbolAddress((void**)&pres,  g_res);
    cudaGetSymbolAddress((void**)&phn,   g_hn);
    cudaGetSymbolAddress((void**)&pxt,   g_xt);
    cudaGetSymbolAddress((void**)&pzt,   g_zt);
    cudaGetSymbolAddress((void**)&pxc,   g_xc);
    cudaGetSymbolAddress((void**)&pdblt, g_dblt);
    cudaGetSymbolAddress((void**)&py,    g_y);

    embed_kernel<<<NTOK, 256>>>(x_src, in_W, ph);

    for (int l = 0; l < 4; l++) {
        ln_kernel<<<NTOK / 8, 256>>>(ph, pres, phn,
                                     norm_w + l * DM, norm_b + l * DM,
                                     (l == 0) ? 1 : 0);
        tc_in<<<dim3(1024 / 64, NTOK / 128), 256, NT_SMEM>>>(
            phn, inproj_W + (size_t)l * 1024 * DM, pxt, pzt);
        conv_t<<<dim3(DI, NB), 256>>>(
            pxt, conv_w + (size_t)l * DI * 4, conv_b + (size_t)l * DI, pxc);
        tc_xp<<<dim3(NS / 64, 1, NB), 256, XP_SMEM>>>(
            xproj_W + (size_t)l * 48 * DI, pxc, pdblt);
        scan_kernel<<<dim3(DI / 8, NB), 128>>>(
            pxc, pzt, pdblt,
            dtproj_W + (size_t)l * DI * 16, dtproj_b + (size_t)l * DI,
            A_log + (size_t)l * DI * DSTATE, D_param + (size_t)l * DI, py);
        tc_op<<<dim3(NS / 64, DM / 128, NB), 256, OP_SMEM>>>(
            outproj_W + (size_t)l * DM * DI, py, ph);
    }

    head_kernel<<<NTOK / 8, 256>>>(ph, out_W, out);
}